// round 9
// baseline (speedup 1.0000x reference)
#include <cuda_runtime.h>
#include <cuda_bf16.h>
#include <math.h>
#include <stdint.h>

// ---------------- constants ----------------
#define Bb 4
#define Cc 48
#define Tt 512
#define Ff 65
#define L0 62
#define L1 509
#define N0 2048
#define N1 260
#define ROWS0 126976
#define ROWS1 132340
#define ROWSMAX 132340
#define CONV_ROWS 133120
#define XU_S  (ROWSMAX*192)
#define XW_S  ((size_t)ROWSMAX*768)
#define HS_S  ((size_t)ROWSMAX*384)
#define TSZ   (Bb*Cc*Tt*Ff)
#define EK    528
#define EPSLN 1e-5f
#define SLAB_BYTES (192*72*4)

// ---------------- device scratch ----------------
__device__ float g_xu[2*XU_S];
__device__ float g_xw[4*XW_S];
__device__ float g_hseq[2*HS_S];
__device__ float g_h[2*4*2048*192];
__device__ float g_c[4*2048*192];
__device__ float g_wihp[8*192*768];
__device__ float g_whhp[8*192*768];
__device__ float g_bp[8*768];
__device__ float g_twt[4*1536*48];
__device__ float g_io[2*TSZ];
__device__ float g_eo[2*TSZ];
__device__ float g_q[(size_t)2*16*512*EK];
__device__ float g_k[(size_t)2*16*512*EK];
__device__ float g_v[2*16*512*780];
__device__ float g_attn[(size_t)2*16*512*512];
__device__ float g_av[2*16*512*780];
__device__ unsigned g_bcnt;
__device__ unsigned g_bgen;

__device__ __forceinline__ float sigf(float x){ return 1.f/(1.f+expf(-x)); }

__device__ __forceinline__ float tf32r(float x){
    uint32_t r; asm("cvt.rna.tf32.f32 %0, %1;" : "=r"(r) : "f"(x));
    return __uint_as_float(r);
}

__device__ __forceinline__ void mma_tf32(float* c, uint32_t a0, uint32_t a1,
                                         uint32_t a2, uint32_t a3,
                                         uint32_t b0, uint32_t b1){
    asm volatile("mma.sync.aligned.m16n8k8.row.col.f32.tf32.tf32.f32 "
        "{%0,%1,%2,%3}, {%4,%5,%6,%7}, {%8,%9}, {%0,%1,%2,%3};"
        : "+f"(c[0]), "+f"(c[1]), "+f"(c[2]), "+f"(c[3])
        : "r"(a0), "r"(a1), "r"(a2), "r"(a3), "r"(b0), "r"(b1));
}

#define MMA_IDS \
    int lane = tid & 31, warp = tid >> 5; \
    int wm = warp >> 1, wn = warp & 1;    \
    int gp = lane >> 2, qn = lane & 3;    \
    int m0 = wm*16 + gp;                  \
    int nb0 = wn*32 + gp;

#define MMA_CHUNK \
    _Pragma("unroll") \
    for (int h8 = 0; h8 < 2; ++h8) { \
        const int kb = h8*8 + qn; \
        uint32_t a0 = As[kb][m0], a1 = As[kb][m0+8]; \
        uint32_t a2 = As[kb+4][m0], a3 = As[kb+4][m0+8]; \
        mma_tf32(acc[0], a0,a1,a2,a3, Bs[kb][nb0],    Bs[kb+4][nb0]); \
        mma_tf32(acc[1], a0,a1,a2,a3, Bs[kb][nb0+8],  Bs[kb+4][nb0+8]); \
        mma_tf32(acc[2], a0,a1,a2,a3, Bs[kb][nb0+16], Bs[kb+4][nb0+16]); \
        mma_tf32(acc[3], a0,a1,a2,a3, Bs[kb][nb0+24], Bs[kb+4][nb0+24]); \
    }

#define LOAD_A_TRANS(Aptr, lda, rowClamp) { \
    int aRow = tid >> 2, ak = (tid & 3)*4; \
    int gr = row0 + aRow; if (gr > (rowClamp)) gr = (rowClamp); \
    float4 v = *(const float4*)&(Aptr)[(size_t)gr*(lda) + kc + ak]; \
    As[ak  ][aRow] = __float_as_uint(v.x); As[ak+1][aRow] = __float_as_uint(v.y); \
    As[ak+2][aRow] = __float_as_uint(v.z); As[ak+3][aRow] = __float_as_uint(v.w); }

#define LOAD_B_DIRECT(Bptr, ldb) { \
    int bk = tid >> 4, bn4 = (tid & 15)*4; \
    float4 v = *(const float4*)&(Bptr)[(size_t)(kc + bk)*(ldb) + col0 + bn4]; \
    Bs[bk][bn4  ] = __float_as_uint(v.x); Bs[bk][bn4+1] = __float_as_uint(v.y); \
    Bs[bk][bn4+2] = __float_as_uint(v.z); Bs[bk][bn4+3] = __float_as_uint(v.w); }

// ---------------- weight packing ----------------
__global__ void pack_weights(const float* __restrict__ LWih, const float* __restrict__ LWhh,
                             const float* __restrict__ Lb,   const float* __restrict__ TW)
{
    int stride = gridDim.x * blockDim.x;
    int t0 = blockIdx.x * blockDim.x + threadIdx.x;
    for (int idx = t0; idx < 8*192*768; idx += stride) {
        int w = idx / (192*768);
        int r = idx - w*(192*768);
        int j = r / 768, col = r - j*768;
        int u = col >> 2, gt = col & 3;
        int g = (w>>2)*2 + ((w>>1)&1);
        int d = w & 1;
        size_t src = ((size_t)(g*2+d)*768 + gt*192 + u);
        g_wihp[idx] = tf32r(LWih[src*192 + j]);
        g_whhp[idx] = tf32r(LWhh[src*192 + j]);
    }
    for (int idx = t0; idx < 8*768; idx += stride) {
        int w = idx / 768, col = idx - w*768;
        int u = col >> 2, gt = col & 3;
        int g = (w>>2)*2 + ((w>>1)&1);
        int d = w & 1;
        g_bp[idx] = Lb[(g*2+d)*768 + gt*192 + u];
    }
    for (int idx = t0; idx < 4*1536*48; idx += stride) {
        int g = idx / (1536*48);
        int r = idx - g*(1536*48);
        int kk = r / 48, o = r - kk*48;
        int k = kk / 384, i = kk - k*384;
        g_twt[idx] = tf32r(TW[(((size_t)g*384 + i)*48 + o)*4 + k]);
    }
}

__global__ void bar_init(){ g_bcnt = 0; g_bgen = 0; }

// ---------------- LN over C + unfold, intra ----------------
__global__ void ln_unfold_intra(const float* __restrict__ x0, const float* __restrict__ x1,
                                const float* __restrict__ ng, const float* __restrict__ nb)
{
    int t = blockIdx.x, b = blockIdx.y, s = blockIdx.z;
    const float* src = s ? x1 : x0;
    __shared__ float zs[48*65];
    __shared__ float mu[65], inv[65];
    int tid = threadIdx.x;
    for (int i = tid; i < 48*65; i += 256) {
        int c = i / 65, f = i - c*65;
        zs[i] = src[((size_t)(b*48 + c)*512 + t)*65 + f];
    }
    __syncthreads();
    if (tid < 65) {
        float s1 = 0.f, s2 = 0.f;
        #pragma unroll
        for (int c = 0; c < 48; ++c) { float v = zs[c*65 + tid]; s1 += v; s2 += v*v; }
        float m = s1 * (1.f/48.f);
        mu[tid] = m;
        inv[tid] = rsqrtf(s2*(1.f/48.f) - m*m + EPSLN);
    }
    __syncthreads();
    size_t n = (size_t)b*512 + t;
    float* outp = g_xu + (size_t)s*XU_S + n*(size_t)L0*192;
    for (int i = tid; i < 48*L0*4; i += 256) {
        int c = i / (L0*4);
        int r = i - c*(L0*4);
        int l = r >> 2, k = r & 3;
        int q = l + k;
        float v = (zs[c*65 + q] - mu[q]) * inv[q] * ng[s*48 + c] + nb[s*48 + c];
        outp[(size_t)l*192 + c*4 + k] = v;
    }
}

// ---------------- LN over C + unfold, inter ----------------
__global__ void ln_unfold_inter(const float* __restrict__ ng, const float* __restrict__ nb)
{
    int t = blockIdx.x, b = blockIdx.y, s = blockIdx.z;
    const float* src = g_io + (size_t)s*TSZ;
    __shared__ float zs[48*65];
    __shared__ float mu[65], inv[65];
    int tid = threadIdx.x;
    for (int i = tid; i < 48*65; i += 256) {
        int c = i / 65, f = i - c*65;
        zs[i] = src[((size_t)(b*48 + c)*512 + t)*65 + f];
    }
    __syncthreads();
    if (tid < 65) {
        float s1 = 0.f, s2 = 0.f;
        #pragma unroll
        for (int c = 0; c < 48; ++c) { float v = zs[c*65 + tid]; s1 += v; s2 += v*v; }
        float m = s1 * (1.f/48.f);
        mu[tid] = m;
        inv[tid] = rsqrtf(s2*(1.f/48.f) - m*m + EPSLN);
    }
    __syncthreads();
    int gi = 2 + s;
    for (int i = tid; i < 48*65; i += 256) {
        int c = i / 65, f = i - c*65;
        float v = (zs[i] - mu[f]) * inv[f] * ng[gi*48 + c] + nb[gi*48 + c];
        size_t n = (size_t)b*65 + f;
        float* outp = g_xu + (size_t)s*XU_S + n*(size_t)L1*192;
        #pragma unroll
        for (int k = 0; k < 4; ++k) {
            int l = t - k;
            if (l >= 0 && l < L1) outp[(size_t)l*192 + c*4 + k] = v;
        }
    }
}

// ---------------- xw = xu @ Wih^T + b (tf32 mma) ----------------
__global__ void __launch_bounds__(256) xw_gemm(int phase, int M)
{
    __shared__ uint32_t As[16][72];
    __shared__ uint32_t Bs[16][72];
    int combo = blockIdx.z;
    int s = combo >> 1;
    const float* A    = g_xu + (size_t)s*XU_S;
    const float* Bw   = g_wihp + (size_t)(phase*4 + combo)*192*768;
    const float* bias = g_bp + (size_t)(phase*4 + combo)*768;
    float* Co = g_xw + (size_t)combo*XW_S;
    int row0 = blockIdx.y*64, col0 = blockIdx.x*64;
    int tid = threadIdx.x;
    MMA_IDS
    float acc[4][4] = {};
    for (int kc = 0; kc < 192; kc += 16) {
        LOAD_A_TRANS(A, 192, M-1)
        LOAD_B_DIRECT(Bw, 768)
        __syncthreads();
        MMA_CHUNK
        __syncthreads();
    }
    int rlo = row0 + wm*16 + gp;
    #pragma unroll
    for (int nn = 0; nn < 4; ++nn) {
        int cb = col0 + wn*32 + nn*8 + 2*qn;
        float b0v = bias[cb], b1v = bias[cb+1];
        if (rlo < M) {
            float2 v = make_float2(acc[nn][0] + b0v, acc[nn][1] + b1v);
            *(float2*)&Co[(size_t)rlo*768 + cb] = v;
        }
        if (rlo + 8 < M) {
            float2 v = make_float2(acc[nn][2] + b0v, acc[nn][3] + b1v);
            *(float2*)&Co[(size_t)(rlo+8)*768 + cb] = v;
        }
    }
}

// ---------------- persistent LSTM: grid-resident, software grid barrier ----------------
// grid (12 colTiles, nRowBlocks, 4 combos); Whh slab persistent in smem.
__global__ void __launch_bounds__(256, 3) lstm_persist(int phase, int Nseq, int Lc,
                                                       int Nsteps, int rowTiles, int nblocks)
{
    extern __shared__ uint32_t Bslab[];   // [192][72]
    int combo = blockIdx.z;
    int s = combo >> 1, d = combo & 1;
    int col0 = blockIdx.x*64;
    int tid = threadIdx.x;
    int lane = tid & 31, warp = tid >> 5;
    int wm = warp >> 1, wn = warp & 1;
    int gp = lane >> 2, qn = lane & 3;
    int odd = qn & 1;

    const float* Bw = g_whhp + (size_t)(phase*4 + combo)*192*768;
    for (int i = tid; i < 192*64; i += 256) {
        int k = i >> 6, n = i & 63;
        Bslab[k*72 + n] = __float_as_uint(Bw[(size_t)k*768 + col0 + n]);
    }

    float* Cst = g_c + (size_t)combo*2048*192;
    float* H0  = g_h + ((size_t)0*4 + combo)*2048*192;
    float* H1  = g_h + ((size_t)1*4 + combo)*2048*192;
    // zero state (h duplicated across col blocks — same value, benign)
    for (int it = 0; it < rowTiles; ++it) {
        int rbase = (blockIdx.y*rowTiles + it)*64;
        for (int i = tid; i < 64*192; i += 256) {
            size_t off = (size_t)(rbase + (i/192))*192 + (i%192);
            H0[off] = 0.f; H1[off] = 0.f;
        }
        for (int i = tid; i < 64*16; i += 256) {
            Cst[(size_t)(rbase + (i>>4))*192 + (col0>>2) + (i&15)] = 0.f;
        }
    }

    const float* XW = g_xw + (size_t)combo*XW_S;
    float* hs = g_hseq + (size_t)s*HS_S;

    unsigned gen = 1;
    // barrier helper inlined
    #define GRID_BAR() { \
        __syncthreads(); \
        if (tid == 0) { \
            __threadfence(); \
            unsigned a = atomicAdd(&g_bcnt, 1); \
            if (a == (unsigned)(nblocks - 1)) { \
                g_bcnt = 0; __threadfence(); \
                atomicExch(&g_bgen, gen); \
            } else { \
                while (*(volatile unsigned*)&g_bgen < gen) {} \
                __threadfence(); \
            } \
        } \
        __syncthreads(); gen++; }

    GRID_BAR()   // state zero visible

    for (int t = 0; t < Nsteps; ++t) {
        int parity = t & 1;
        const float* Ah = parity ? H1 : H0;
        float* Ho       = parity ? H0 : H1;
        int tt = d ? (Lc - 1 - t) : t;
        for (int it = 0; it < rowTiles; ++it) {
            int rbase = (blockIdx.y*rowTiles + it)*64;
            int rlo = rbase + wm*16 + gp;
            int rhi = rlo + 8;
            int rloC = rlo < Nseq ? rlo : Nseq - 1;
            int rhiC = rhi < Nseq ? rhi : Nseq - 1;
            const float* A0 = Ah + (size_t)rloC*192;
            const float* A1 = Ah + (size_t)rhiC*192;
            float acc[4][4] = {};
            int nb0 = wn*32 + gp;
            #pragma unroll
            for (int k8 = 0; k8 < 24; ++k8) {
                int k0 = k8*8;
                uint32_t a0 = __float_as_uint(__ldcg(A0 + k0 + qn));
                uint32_t a1 = __float_as_uint(__ldcg(A1 + k0 + qn));
                uint32_t a2 = __float_as_uint(__ldcg(A0 + k0 + qn + 4));
                uint32_t a3 = __float_as_uint(__ldcg(A1 + k0 + qn + 4));
                const uint32_t* Bk0 = &Bslab[(k0 + qn)*72];
                const uint32_t* Bk1 = &Bslab[(k0 + qn + 4)*72];
                mma_tf32(acc[0], a0,a1,a2,a3, Bk0[nb0],    Bk1[nb0]);
                mma_tf32(acc[1], a0,a1,a2,a3, Bk0[nb0+8],  Bk1[nb0+8]);
                mma_tf32(acc[2], a0,a1,a2,a3, Bk0[nb0+16], Bk1[nb0+16]);
                mma_tf32(acc[3], a0,a1,a2,a3, Bk0[nb0+24], Bk1[nb0+24]);
            }
            // epilogue: lane^1 holds the other gate pair of the same unit
            int row = odd ? rhi : rlo;
            #pragma unroll
            for (int nn = 0; nn < 4; ++nn) {
                float sx0 = __shfl_xor_sync(0xffffffffu, acc[nn][0], 1);
                float sx1 = __shfl_xor_sync(0xffffffffu, acc[nn][1], 1);
                float sx2 = __shfl_xor_sync(0xffffffffu, acc[nn][2], 1);
                float sx3 = __shfl_xor_sync(0xffffffffu, acc[nn][3], 1);
                float gi, gf, gg, go;
                if (!odd) { gi = acc[nn][0]; gf = acc[nn][1]; gg = sx0; go = sx1; }
                else      { gi = sx2; gf = sx3; gg = acc[nn][2]; go = acc[nn][3]; }
                if (row < Nseq) {
                    int ug = (col0 >> 2) + wn*8 + nn*2 + (qn >> 1);
                    float4 xv = *(const float4*)&XW[((size_t)row*Lc + tt)*768 + ug*4];
                    float I = gi + xv.x, F = gf + xv.y, G = gg + xv.z, O = go + xv.w;
                    float cp = Cst[(size_t)row*192 + ug];
                    float cn = sigf(F)*cp + sigf(I)*tanhf(G);
                    float hn = sigf(O)*tanhf(cn);
                    Cst[(size_t)row*192 + ug] = cn;
                    Ho[(size_t)row*192 + ug]  = hn;
                    hs[((size_t)row*Lc + tt)*384 + d*192 + ug] = hn;
                }
            }
        }
        GRID_BAR()
    }
    #undef GRID_BAR
}

// ---------------- convT1d gather-GEMM + bias + residual ----------------
__global__ void __launch_bounds__(256) convt_gemm(int phase, const float* __restrict__ Tb,
                                                  const float* __restrict__ x0, const float* __restrict__ x1)
{
    __shared__ uint32_t As[16][72];
    __shared__ uint32_t Bs[16][72];
    int s = blockIdx.z;
    int Lc   = phase ? L1 : L0;
    int Qlen = phase ? 512 : 65;
    const float* hs = g_hseq + (size_t)s*HS_S;
    const float* Bw = g_twt + (size_t)(phase*2 + s)*1536*48;
    int row0 = blockIdx.y*64;
    int tid = threadIdx.x;
    MMA_IDS
    float acc[4][4] = {};
    for (int kc = 0; kc < 1536; kc += 16) {
        int ktap = kc / 384;
        int i0 = kc - ktap*384;
        {
            int aRow = tid >> 2, ak = (tid & 3)*4;
            int gr = row0 + aRow;
            int n = gr / Qlen, q = gr - n*Qlen;
            int l = q - ktap;
            float4 v = make_float4(0.f, 0.f, 0.f, 0.f);
            if (l >= 0 && l < Lc)
                v = *(const float4*)&hs[((size_t)n*Lc + l)*384 + i0 + ak];
            As[ak  ][aRow] = __float_as_uint(v.x); As[ak+1][aRow] = __float_as_uint(v.y);
            As[ak+2][aRow] = __float_as_uint(v.z); As[ak+3][aRow] = __float_as_uint(v.w);
        }
        {
            int bk = tid >> 4, bn4 = (tid & 15)*4;
            float4 v = make_float4(0.f, 0.f, 0.f, 0.f);
            if (bn4 < 48) v = *(const float4*)&Bw[(size_t)(kc + bk)*48 + bn4];
            Bs[bk][bn4  ] = __float_as_uint(v.x); Bs[bk][bn4+1] = __float_as_uint(v.y);
            Bs[bk][bn4+2] = __float_as_uint(v.z); Bs[bk][bn4+3] = __float_as_uint(v.w);
        }
        __syncthreads();
        MMA_CHUNK
        __syncthreads();
    }
    int g = phase*2 + s;
    int rlo = row0 + wm*16 + gp;
    #pragma unroll
    for (int nn = 0; nn < 4; ++nn) {
        int cb = wn*32 + nn*8 + 2*qn;
        #pragma unroll
        for (int half = 0; half < 2; ++half) {
            int row = rlo + half*8;
            int n = row / Qlen, q = row - n*Qlen;
            #pragma unroll
            for (int j = 0; j < 2; ++j) {
                int c = cb + j;
                if (c < 48) {
                    float v = acc[nn][half*2 + j] + Tb[g*48 + c];
                    if (phase == 0) {
                        int b = n >> 9, tpos = n & 511;
                        size_t oi = ((size_t)(b*48 + c)*512 + tpos)*65 + q;
                        const float* res = s ? x1 : x0;
                        g_io[(size_t)s*TSZ + oi] = v + res[oi];
                    } else {
                        int b = n / 65, f = n - b*65;
                        size_t oi = ((size_t)(b*48 + c)*512 + q)*65 + f;
                        g_eo[(size_t)s*TSZ + oi] = v + g_io[(size_t)s*TSZ + oi];
                    }
                }
            }
        }
    }
}

// ---------------- q/k/v head projections + leaky + LN ----------------
__global__ void __launch_bounds__(256) qkv_kernel(
    const float* __restrict__ AWqk, const float* __restrict__ Abqk, const float* __restrict__ Aaqk,
    const float* __restrict__ Agqk, const float* __restrict__ Abgqk,
    const float* __restrict__ AWv,  const float* __restrict__ Abv,  const float* __restrict__ Aav,
    const float* __restrict__ Agv,  const float* __restrict__ Abgv)
{
    int t = blockIdx.x, b = blockIdx.y, s = blockIdx.z, tid = threadIdx.x;
    int lane = tid & 31, warp = tid >> 5;
    __shared__ float zs[3120];
    __shared__ float buf[780];
    __shared__ float red[32];
    const float* z = g_eo + (size_t)s*TSZ;
    for (int i = tid; i < 3120; i += 256) {
        int c = i / 65, f = i - c*65;
        zs[i] = z[((size_t)(b*48 + c)*512 + t)*65 + f];
    }
    __syncthreads();
    for (int grp = 0; grp < 12; ++grp) {
        int tensor = grp >> 2, h = grp & 3;
        int nvals;
        const float *W, *bb, *gam, *bet;
        float alpha;
        float* outp;
        bool pad = false;
        if (tensor < 2) {
            nvals = 520;
            int hh = (s*2 + tensor)*4 + h;
            W = AWqk + (size_t)hh*8*48; bb = Abqk + hh*8; alpha = Aaqk[hh];
            gam = Agqk + (size_t)hh*8*65; bet = Abgqk + (size_t)hh*8*65;
            outp = (tensor == 0 ? g_q : g_k) + ((size_t)((s*16 + b*4 + h)*512) + t)*EK;
            pad = true;
        } else {
            nvals = 780;
            int hh = s*4 + h;
            W = AWv + (size_t)hh*12*48; bb = Abv + hh*12; alpha = Aav[hh];
            gam = Agv + (size_t)hh*12*65; bet = Abgv + (size_t)hh*12*65;
            outp = g_v + ((size_t)((s*16 + b*4 + h)*512) + t)*780;
        }
        float ls = 0.f, lq = 0.f;
        for (int idx = tid; idx < nvals; idx += 256) {
            int e = idx / 65, f = idx - e*65;
            float a = bb[e];
            const float* wr = W + e*48;
            #pragma unroll
            for (int c = 0; c < 48; ++c) a += zs[c*65 + f]*wr[c];
            a = a >= 0.f ? a : alpha*a;
            buf[idx] = a; ls += a; lq += a*a;
        }
        #pragma unroll
        for (int o = 16; o; o >>= 1) {
            ls += __shfl_xor_sync(0xffffffffu, ls, o);
            lq += __shfl_xor_sync(0xffffffffu, lq, o);
        }
        if (lane == 0) { red[warp] = ls; red[8 + warp] = lq; }
        __syncthreads();
        if (tid == 0) {
            float a = 0.f, c = 0.f;
            #pragma unroll
            for (int i = 0; i < 8; ++i) { a += red[i]; c += red[8 + i]; }
            red[16] = a; red[17] = c;
        }
        __syncthreads();
        float mu = red[16] / nvals;
        float inv = rsqrtf(red[17] / nvals - mu*mu + EPSLN);
        for (int idx = tid; idx < nvals; idx += 256)
            outp[idx] = (buf[idx] - mu)*inv*gam[idx] + bet[idx];
        if (pad && tid < EK - 520) outp[520 + tid] = 0.f;
        __syncthreads();
    }
}

// ---------------- QK^T (scaled) ----------------
__global__ void __launch_bounds__(256) qk_gemm()
{
    __shared__ uint32_t As[16][72];
    __shared__ uint32_t Bs[16][72];
    int bz = blockIdx.z;
    const float* Q  = g_q + (size_t)bz*512*EK;
    const float* Kf = g_k + (size_t)bz*512*EK;
    float* Co = g_attn + (size_t)bz*512*512;
    int row0 = blockIdx.y*64, col0 = blockIdx.x*64;
    int tid = threadIdx.x;
    MMA_IDS
    float acc[4][4] = {};
    for (int kc = 0; kc < EK; kc += 16) {
        LOAD_A_TRANS(Q, EK, 511)
        {
            int bRow = tid >> 2, bk = (tid & 3)*4;
            float4 v = *(const float4*)&Kf[(size_t)(col0 + bRow)*EK + kc + bk];
            Bs[bk  ][bRow] = __float_as_uint(v.x); Bs[bk+1][bRow] = __float_as_uint(v.y);
            Bs[bk+2][bRow] = __float_as_uint(v.z); Bs[bk+3][bRow] = __float_as_uint(v.w);
        }
        __syncthreads();
        MMA_CHUNK
        __syncthreads();
    }
    float rs = rsqrtf(520.f);
    int rlo = row0 + wm*16 + gp;
    #pragma unroll
    for (int nn = 0; nn < 4; ++nn) {
        int cb = col0 + wn*32 + nn*8 + 2*qn;
        *(float2*)&Co[(size_t)rlo*512 + cb]     = make_float2(acc[nn][0]*rs, acc[nn][1]*rs);
        *(float2*)&Co[(size_t)(rlo+8)*512 + cb] = make_float2(acc[nn][2]*rs, acc[nn][3]*rs);
    }
}

// ---------------- row softmax ----------------
__global__ void __launch_bounds__(256) softmax_rows()
{
    int row = blockIdx.x, bz = blockIdx.y, tid = threadIdx.x;
    float* p = g_attn + (size_t)bz*512*512 + (size_t)row*512;
    __shared__ float sm[512];
    __shared__ float red[256];
    sm[tid] = p[tid]; sm[tid + 256] = p[tid + 256];
    red[tid] = fmaxf(sm[tid], sm[tid + 256]);
    __syncthreads();
    for (int st = 128; st > 0; st >>= 1) {
        if (tid < st) red[tid] = fmaxf(red[tid], red[tid + st]);
        __syncthreads();
    }
    float mx = red[0];
    __syncthreads();
    float e0 = expf(sm[tid] - mx), e1 = expf(sm[tid + 256] - mx);
    red[tid] = e0 + e1;
    __syncthreads();
    for (int st = 128; st > 0; st >>= 1) {
        if (tid < st) red[tid] += red[tid + st];
        __syncthreads();
    }
    float invs = 1.f / red[0];
    p[tid] = e0*invs; p[tid + 256] = e1*invs;
}

// ---------------- P @ V ----------------
__global__ void __launch_bounds__(256) pv_gemm()
{
    __shared__ uint32_t As[16][72];
    __shared__ uint32_t Bs[16][72];
    int bz = blockIdx.z;
    const float* A  = g_attn + (size_t)bz*512*512;
    const float* Bv = g_v + (size_t)bz*512*780;
    float* Co = g_av + (size_t)bz*512*780;
    int row0 = blockIdx.y*64, col0 = blockIdx.x*64;
    int tid = threadIdx.x;
    MMA_IDS
    float acc[4][4] = {};
    for (int kc = 0; kc < 512; kc += 16) {
        LOAD_A_TRANS(A, 512, 511)
        {
            int bk = tid >> 4, bn4 = (tid & 15)*4;
            int col = col0 + bn4;
            float4 v;
            if (col + 3 < 780) {
                v = *(const float4*)&Bv[(size_t)(kc + bk)*780 + col];
            } else {
                v.x = (col     < 780) ? Bv[(size_t)(kc + bk)*780 + col]     : 0.f;
                v.y = (col + 1 < 780) ? Bv[(size_t)(kc + bk)*780 + col + 1] : 0.f;
                v.z = (col + 2 < 780) ? Bv[(size_t)(kc + bk)*780 + col + 2] : 0.f;
                v.w = (col + 3 < 780) ? Bv[(size_t)(kc + bk)*780 + col + 3] : 0.f;
            }
            Bs[bk][bn4  ] = __float_as_uint(v.x); Bs[bk][bn4+1] = __float_as_uint(v.y);
            Bs[bk][bn4+2] = __float_as_uint(v.z); Bs[bk][bn4+3] = __float_as_uint(v.w);
        }
        __syncthreads();
        MMA_CHUNK
        __syncthreads();
    }
    int rlo = row0 + wm*16 + gp;
    #pragma unroll
    for (int nn = 0; nn < 4; ++nn) {
        int cb = col0 + wn*32 + nn*8 + 2*qn;
        #pragma unroll
        for (int j = 0; j < 2; ++j) {
            int col = cb + j;
            if (col < 780) {
                Co[(size_t)rlo*780 + col]     = acc[nn][j];
                Co[(size_t)(rlo+8)*780 + col] = acc[nn][2 + j];
            }
        }
    }
}

// ---------------- output projection + leaky + LN + residual ----------------
__global__ void __launch_bounds__(256) outproj_kernel(
    const float* __restrict__ AWp, const float* __restrict__ Abp, const float* __restrict__ Aap,
    const float* __restrict__ Agp, const float* __restrict__ Abgp, float* __restrict__ dout)
{
    int t = blockIdx.x, b = blockIdx.y, s = blockIdx.z, tid = threadIdx.x;
    int lane = tid & 31, warp = tid >> 5;
    __shared__ float os[3120];
    __shared__ float buf[3120];
    __shared__ float red[32];
    for (int i = tid; i < 3120; i += 256) {
        int c = i / 65, f = i - c*65;
        int h = c / 12, dv = c - h*12;
        os[i] = g_av[((size_t)((s*16 + b*4 + h)*512) + t)*780 + dv*65 + f];
    }
    __syncthreads();
    float alpha = Aap[s];
    float ls = 0.f, lq = 0.f;
    for (int idx = tid; idx < 3120; idx += 256) {
        int o = idx / 65, f = idx - o*65;
        float a = Abp[s*48 + o];
        const float* wr = AWp + (size_t)(s*48 + o)*48;
        #pragma unroll
        for (int c = 0; c < 48; ++c) a += os[c*65 + f]*wr[c];
        a = a >= 0.f ? a : alpha*a;
        buf[idx] = a; ls += a; lq += a*a;
    }
    #pragma unroll
    for (int o = 16; o; o >>= 1) {
        ls += __shfl_xor_sync(0xffffffffu, ls, o);
        lq += __shfl_xor_sync(0xffffffffu, lq, o);
    }
    if (lane == 0) { red[warp] = ls; red[8 + warp] = lq; }
    __syncthreads();
    if (tid == 0) {
        float a = 0.f, c = 0.f;
        #pragma unroll
        for (int i = 0; i < 8; ++i) { a += red[i]; c += red[8 + i]; }
        red[16] = a; red[17] = c;
    }
    __syncthreads();
    float mu = red[16] / 3120.f;
    float inv = rsqrtf(red[17] / 3120.f - mu*mu + EPSLN);
    for (int idx = tid; idx < 3120; idx += 256) {
        int o = idx / 65, f = idx - o*65;
        float v = (buf[idx] - mu)*inv*Agp[(s*48 + o)*65 + f] + Abgp[(s*48 + o)*65 + f]
                + g_eo[(size_t)s*TSZ + ((size_t)(b*48 + o)*512 + t)*65 + f];
        dout[(((size_t)(s*4 + b)*48 + o)*512 + t)*65 + f] = v;
    }
}

// ---------------- host launch ----------------
extern "C" void kernel_launch(void* const* d_in, const int* in_sizes, int n_in,
                              void* d_out, int out_size)
{
    const float* x     = (const float*)d_in[0];
    const float* c2    = (const float*)d_in[1];
    const float* ng    = (const float*)d_in[2];
    const float* nb    = (const float*)d_in[3];
    const float* LWih  = (const float*)d_in[4];
    const float* LWhh  = (const float*)d_in[5];
    const float* Lb    = (const float*)d_in[6];
    const float* TW    = (const float*)d_in[7];
    const float* Tb    = (const float*)d_in[8];
    const float* AWqk  = (const float*)d_in[9];
    const float* Abqk  = (const float*)d_in[10];
    const float* Aaqk  = (const float*)d_in[11];
    const float* Agqk  = (const float*)d_in[12];
    const float* Abgqk = (const float*)d_in[13];
    const float* AWv   = (const float*)d_in[14];
    const float* Abv   = (const float*)d_in[15];
    const float* Aav   = (const float*)d_in[16];
    const float* Agv   = (const float*)d_in[17];
    const float* Abgv  = (const float*)d_in[18];
    const float* AWp   = (const float*)d_in[19];
    const float* Abp   = (const float*)d_in[20];
    const float* Aap   = (const float*)d_in[21];
    const float* Agp   = (const float*)d_in[22];
    const float* Abgp  = (const float*)d_in[23];
    float* out = (float*)d_out;

    cudaFuncSetAttribute(lstm_persist, cudaFuncAttributeMaxDynamicSharedMemorySize, SLAB_BYTES);

    pack_weights<<<512, 256>>>(LWih, LWhh, Lb, TW);

    // ---- phase 0: intra ----
    ln_unfold_intra<<<dim3(512, 4, 2), 256>>>(x, c2, ng, nb);
    xw_gemm<<<dim3(12, (ROWS0 + 63)/64, 4), 256>>>(0, ROWS0);
    bar_init<<<1, 1>>>();
    lstm_persist<<<dim3(12, 8, 4), 256, SLAB_BYTES>>>(0, N0, L0, L0, 4, 12*8*4);
    convt_gemm<<<dim3(1, CONV_ROWS/64, 2), 256>>>(0, Tb, x, c2);

    // ---- phase 1: inter ----
    ln_unfold_inter<<<dim3(512, 4, 2), 256>>>(ng, nb);
    xw_gemm<<<dim3(12, (ROWS1 + 63)/64, 4), 256>>>(1, ROWS1);
    bar_init<<<1, 1>>>();
    lstm_persist<<<dim3(12, 5, 4), 256, SLAB_BYTES>>>(1, N1, L1, L1, 1, 12*5*4);
    convt_gemm<<<dim3(1, CONV_ROWS/64, 2), 256>>>(1, Tb, x, c2);

    // ---- attention ----
    qkv_kernel<<<dim3(512, 4, 2), 256>>>(AWqk, Abqk, Aaqk, Agqk, Abgqk,
                                         AWv, Abv, Aav, Agv, Abgv);
    qk_gemm<<<dim3(8, 8, 32), 256>>>();
    softmax_rows<<<dim3(512, 32), 256>>>();
    pv_gemm<<<dim3(13, 8, 32), 256>>>();
    outproj_kernel<<<dim3(512, 4, 2), 256>>>(AWp, Abp, Aap, Agp, Abgp, out);
}

// round 10
// speedup vs baseline: 1.6259x; 1.6259x over previous
#include <cuda_runtime.h>
#include <cuda_bf16.h>
#include <math.h>
#include <stdint.h>

// ---------------- constants ----------------
#define Bb 4
#define Cc 48
#define Tt 512
#define Ff 65
#define L0 62
#define L1 509
#define N0 2048
#define N1 260
#define ROWS0 126976
#define ROWS1 132340
#define ROWSMAX 132340
#define CONV_ROWS 133120
#define XU_S  (ROWSMAX*192)
#define XW_S  ((size_t)ROWSMAX*768)
#define HS_S  ((size_t)ROWSMAX*384)
#define TSZ   (Bb*Cc*Tt*Ff)
#define EK    528
#define EPSLN 1e-5f

// ---------------- device scratch ----------------
__device__ float g_xu[2*XU_S];
__device__ float g_xw[4*XW_S];
__device__ float g_hseq[2*HS_S];
__device__ float g_h[2*4*2048*192];
__device__ float g_c[4*2048*192];
__device__ float g_wihp[8*192*768];
__device__ float g_whhp[8*192*768];
__device__ float g_bp[8*768];
__device__ float g_twt[4*1536*48];
__device__ float g_io[2*TSZ];
__device__ float g_eo[2*TSZ];
__device__ float g_q[(size_t)2*16*512*EK];
__device__ float g_k[(size_t)2*16*512*EK];
__device__ float g_v[2*16*512*780];
__device__ float g_attn[(size_t)2*16*512*512];
__device__ float g_av[2*16*512*780];

__device__ __forceinline__ float sigf(float x){ return 1.f/(1.f+expf(-x)); }

__device__ __forceinline__ float tf32r(float x){
    uint32_t r; asm("cvt.rna.tf32.f32 %0, %1;" : "=r"(r) : "f"(x));
    return __uint_as_float(r);
}

__device__ __forceinline__ void mma_tf32(float* c, uint32_t a0, uint32_t a1,
                                         uint32_t a2, uint32_t a3,
                                         uint32_t b0, uint32_t b1){
    asm volatile("mma.sync.aligned.m16n8k8.row.col.f32.tf32.tf32.f32 "
        "{%0,%1,%2,%3}, {%4,%5,%6,%7}, {%8,%9}, {%0,%1,%2,%3};"
        : "+f"(c[0]), "+f"(c[1]), "+f"(c[2]), "+f"(c[3])
        : "r"(a0), "r"(a1), "r"(a2), "r"(a3), "r"(b0), "r"(b1));
}

// cp.async helpers
__device__ __forceinline__ void cp16(void* smem, const void* gmem){
    uint32_t s = (uint32_t)__cvta_generic_to_shared(smem);
    asm volatile("cp.async.ca.shared.global [%0], [%1], 16;\n" :: "r"(s), "l"(gmem) : "memory");
}
__device__ __forceinline__ void cp16z(void* smem, const void* gmem, bool valid){
    uint32_t s = (uint32_t)__cvta_generic_to_shared(smem);
    int sz = valid ? 16 : 0;
    asm volatile("cp.async.ca.shared.global [%0], [%1], 16, %2;\n" :: "r"(s), "l"(gmem), "r"(sz) : "memory");
}
__device__ __forceinline__ void cp_commit(){ asm volatile("cp.async.commit_group;\n" ::: "memory"); }
__device__ __forceinline__ void cp_wait0(){ asm volatile("cp.async.wait_group 0;\n" ::: "memory"); }
__device__ __forceinline__ void cp_wait1(){ asm volatile("cp.async.wait_group 1;\n" ::: "memory"); }

#define MMA_IDS \
    int lane = tid & 31, warp = tid >> 5; \
    int wm = warp >> 1, wn = warp & 1;    \
    int gp = lane >> 2, qn = lane & 3;    \
    int m0 = wm*16 + gp;                  \
    int nb0 = wn*32 + gp;

// ---- old-style (16-deep transposed) staging for qk/pv ----
#define MMA_CHUNK \
    _Pragma("unroll") \
    for (int h8 = 0; h8 < 2; ++h8) { \
        const int kb = h8*8 + qn; \
        uint32_t a0 = As[kb][m0], a1 = As[kb][m0+8]; \
        uint32_t a2 = As[kb+4][m0], a3 = As[kb+4][m0+8]; \
        mma_tf32(acc[0], a0,a1,a2,a3, Bs[kb][nb0],    Bs[kb+4][nb0]); \
        mma_tf32(acc[1], a0,a1,a2,a3, Bs[kb][nb0+8],  Bs[kb+4][nb0+8]); \
        mma_tf32(acc[2], a0,a1,a2,a3, Bs[kb][nb0+16], Bs[kb+4][nb0+16]); \
        mma_tf32(acc[3], a0,a1,a2,a3, Bs[kb][nb0+24], Bs[kb+4][nb0+24]); \
    }

#define LOAD_A_TRANS(Aptr, lda, rowClamp) { \
    int aRow = tid >> 2, ak = (tid & 3)*4; \
    int gr = row0 + aRow; if (gr > (rowClamp)) gr = (rowClamp); \
    float4 v = *(const float4*)&(Aptr)[(size_t)gr*(lda) + kc + ak]; \
    As[ak  ][aRow] = __float_as_uint(v.x); As[ak+1][aRow] = __float_as_uint(v.y); \
    As[ak+2][aRow] = __float_as_uint(v.z); As[ak+3][aRow] = __float_as_uint(v.w); }

// ---- new 32-deep double-buffered staging (As untransposed) ----
// As2[2][64][36], Bs2[2][32][72]
#define LOAD_A32(buf, Aptr, lda, rowClamp, kcc) { \
    int idx = tid; \
    _Pragma("unroll") for (int rep = 0; rep < 2; ++rep) { \
        int row = idx >> 3, seg = idx & 7; \
        int gr = row0 + row; if (gr > (rowClamp)) gr = (rowClamp); \
        cp16(&As2[buf][row][seg*4], &(Aptr)[(size_t)gr*(lda) + (kcc) + seg*4]); \
        idx += 256; } }

#define LOAD_B32(buf, Bptr, ldb, kcc) { \
    int idx = tid; \
    _Pragma("unroll") for (int rep = 0; rep < 2; ++rep) { \
        int k = idx >> 4, seg = idx & 15; \
        cp16(&Bs2[buf][k][seg*4], &(Bptr)[(size_t)((kcc) + k)*(ldb) + col0 + seg*4]); \
        idx += 256; } }

#define MMA32(buf) \
    _Pragma("unroll") for (int k8 = 0; k8 < 4; ++k8) { \
        int kb = k8*8 + qn; \
        uint32_t a0 = As2[buf][m0][kb],   a1 = As2[buf][m0+8][kb]; \
        uint32_t a2 = As2[buf][m0][kb+4], a3 = As2[buf][m0+8][kb+4]; \
        const uint32_t* B0 = &Bs2[buf][kb][0]; \
        const uint32_t* B1 = &Bs2[buf][kb+4][0]; \
        mma_tf32(acc[0], a0,a1,a2,a3, B0[nb0],    B1[nb0]); \
        mma_tf32(acc[1], a0,a1,a2,a3, B0[nb0+8],  B1[nb0+8]); \
        mma_tf32(acc[2], a0,a1,a2,a3, B0[nb0+16], B1[nb0+16]); \
        mma_tf32(acc[3], a0,a1,a2,a3, B0[nb0+24], B1[nb0+24]); \
    }

// ---------------- weight packing ----------------
__global__ void pack_weights(const float* __restrict__ LWih, const float* __restrict__ LWhh,
                             const float* __restrict__ Lb,   const float* __restrict__ TW)
{
    int stride = gridDim.x * blockDim.x;
    int t0 = blockIdx.x * blockDim.x + threadIdx.x;
    for (int idx = t0; idx < 8*192*768; idx += stride) {
        int w = idx / (192*768);
        int r = idx - w*(192*768);
        int j = r / 768, col = r - j*768;
        int u = col >> 2, gt = col & 3;
        int g = (w>>2)*2 + ((w>>1)&1);
        int d = w & 1;
        size_t src = ((size_t)(g*2+d)*768 + gt*192 + u);
        g_wihp[idx] = tf32r(LWih[src*192 + j]);
        g_whhp[idx] = tf32r(LWhh[src*192 + j]);
    }
    for (int idx = t0; idx < 8*768; idx += stride) {
        int w = idx / 768, col = idx - w*768;
        int u = col >> 2, gt = col & 3;
        int g = (w>>2)*2 + ((w>>1)&1);
        int d = w & 1;
        g_bp[idx] = Lb[(g*2+d)*768 + gt*192 + u];
    }
    for (int idx = t0; idx < 4*1536*48; idx += stride) {
        int g = idx / (1536*48);
        int r = idx - g*(1536*48);
        int kk = r / 48, o = r - kk*48;
        int k = kk / 384, i = kk - k*384;
        g_twt[idx] = tf32r(TW[(((size_t)g*384 + i)*48 + o)*4 + k]);
    }
}

__global__ void zero_state()
{
    int stride = gridDim.x * blockDim.x;
    int t0 = blockIdx.x * blockDim.x + threadIdx.x;
    for (int i = t0; i < 2*4*2048*192; i += stride) g_h[i] = 0.f;
    for (int i = t0; i < 4*2048*192;   i += stride) g_c[i] = 0.f;
}

// ---------------- LN over C + unfold, intra ----------------
__global__ void ln_unfold_intra(const float* __restrict__ x0, const float* __restrict__ x1,
                                const float* __restrict__ ng, const float* __restrict__ nb)
{
    int t = blockIdx.x, b = blockIdx.y, s = blockIdx.z;
    const float* src = s ? x1 : x0;
    __shared__ float zs[48*65];
    __shared__ float mu[65], inv[65];
    int tid = threadIdx.x;
    for (int i = tid; i < 48*65; i += 256) {
        int c = i / 65, f = i - c*65;
        zs[i] = src[((size_t)(b*48 + c)*512 + t)*65 + f];
    }
    __syncthreads();
    if (tid < 65) {
        float s1 = 0.f, s2 = 0.f;
        #pragma unroll
        for (int c = 0; c < 48; ++c) { float v = zs[c*65 + tid]; s1 += v; s2 += v*v; }
        float m = s1 * (1.f/48.f);
        mu[tid] = m;
        inv[tid] = rsqrtf(s2*(1.f/48.f) - m*m + EPSLN);
    }
    __syncthreads();
    size_t n = (size_t)b*512 + t;
    float* outp = g_xu + (size_t)s*XU_S + n*(size_t)L0*192;
    for (int i = tid; i < 48*L0*4; i += 256) {
        int c = i / (L0*4);
        int r = i - c*(L0*4);
        int l = r >> 2, k = r & 3;
        int q = l + k;
        float v = (zs[c*65 + q] - mu[q]) * inv[q] * ng[s*48 + c] + nb[s*48 + c];
        outp[(size_t)l*192 + c*4 + k] = v;
    }
}

// ---------------- LN over C + unfold, inter ----------------
__global__ void ln_unfold_inter(const float* __restrict__ ng, const float* __restrict__ nb)
{
    int t = blockIdx.x, b = blockIdx.y, s = blockIdx.z;
    const float* src = g_io + (size_t)s*TSZ;
    __shared__ float zs[48*65];
    __shared__ float mu[65], inv[65];
    int tid = threadIdx.x;
    for (int i = tid; i < 48*65; i += 256) {
        int c = i / 65, f = i - c*65;
        zs[i] = src[((size_t)(b*48 + c)*512 + t)*65 + f];
    }
    __syncthreads();
    if (tid < 65) {
        float s1 = 0.f, s2 = 0.f;
        #pragma unroll
        for (int c = 0; c < 48; ++c) { float v = zs[c*65 + tid]; s1 += v; s2 += v*v; }
        float m = s1 * (1.f/48.f);
        mu[tid] = m;
        inv[tid] = rsqrtf(s2*(1.f/48.f) - m*m + EPSLN);
    }
    __syncthreads();
    int gi = 2 + s;
    for (int i = tid; i < 48*65; i += 256) {
        int c = i / 65, f = i - c*65;
        float v = (zs[i] - mu[f]) * inv[f] * ng[gi*48 + c] + nb[gi*48 + c];
        size_t n = (size_t)b*65 + f;
        float* outp = g_xu + (size_t)s*XU_S + n*(size_t)L1*192;
        #pragma unroll
        for (int k = 0; k < 4; ++k) {
            int l = t - k;
            if (l >= 0 && l < L1) outp[(size_t)l*192 + c*4 + k] = v;
        }
    }
}

// ---------------- xw = xu @ Wih^T + b (double-buffered cp.async tf32 mma) ----------------
__global__ void __launch_bounds__(256) xw_gemm(int phase, int M)
{
    __shared__ uint32_t As2[2][64][36];
    __shared__ uint32_t Bs2[2][32][72];
    int combo = blockIdx.z;
    int s = combo >> 1;
    const float* A    = g_xu + (size_t)s*XU_S;
    const float* Bw   = g_wihp + (size_t)(phase*4 + combo)*192*768;
    const float* bias = g_bp + (size_t)(phase*4 + combo)*768;
    float* Co = g_xw + (size_t)combo*XW_S;
    int row0 = blockIdx.y*64, col0 = blockIdx.x*64;
    int tid = threadIdx.x;
    MMA_IDS
    float acc[4][4] = {};
    LOAD_A32(0, A, 192, M-1, 0)
    LOAD_B32(0, Bw, 768, 0)
    cp_commit();
    #pragma unroll
    for (int c = 0; c < 6; ++c) {
        int cur = c & 1;
        if (c < 5) {
            LOAD_A32(cur^1, A, 192, M-1, (c+1)*32)
            LOAD_B32(cur^1, Bw, 768, (c+1)*32)
            cp_commit();
            cp_wait1();
        } else cp_wait0();
        __syncthreads();
        MMA32(cur)
        __syncthreads();
    }
    int rlo = row0 + wm*16 + gp;
    #pragma unroll
    for (int nn = 0; nn < 4; ++nn) {
        int cb = col0 + wn*32 + nn*8 + 2*qn;
        float b0v = bias[cb], b1v = bias[cb+1];
        if (rlo < M) {
            float2 v = make_float2(acc[nn][0] + b0v, acc[nn][1] + b1v);
            *(float2*)&Co[(size_t)rlo*768 + cb] = v;
        }
        if (rlo + 8 < M) {
            float2 v = make_float2(acc[nn][2] + b0v, acc[nn][3] + b1v);
            *(float2*)&Co[(size_t)(rlo+8)*768 + cb] = v;
        }
    }
}

// ---------------- fused LSTM step (double-buffered, shfl gate epilogue) ----------------
__global__ void __launch_bounds__(256) lstm_step(int t, int phase, int parity, int Nseq, int Lc)
{
    __shared__ uint32_t As2[2][64][36];
    __shared__ uint32_t Bs2[2][32][72];
    int combo = blockIdx.z;
    int s = combo >> 1, d = combo & 1;
    int tt = d ? (Lc - 1 - t) : t;
    const float* Ah = g_h + ((size_t)parity*4 + combo)*2048*192;
    float* Ho       = g_h + ((size_t)(parity ^ 1)*4 + combo)*2048*192;
    float* Cst      = g_c + (size_t)combo*2048*192;
    const float* Bw = g_whhp + (size_t)(phase*4 + combo)*192*768;
    const float* XW = g_xw + (size_t)combo*XW_S;
    float* hs = g_hseq + (size_t)s*HS_S;
    int row0 = blockIdx.y*64, col0 = blockIdx.x*64;
    int tid = threadIdx.x;
    MMA_IDS
    int odd = qn & 1;
    float acc[4][4] = {};
    LOAD_A32(0, Ah, 192, Nseq-1, 0)
    LOAD_B32(0, Bw, 768, 0)
    cp_commit();
    #pragma unroll
    for (int c = 0; c < 6; ++c) {
        int cur = c & 1;
        if (c < 5) {
            LOAD_A32(cur^1, Ah, 192, Nseq-1, (c+1)*32)
            LOAD_B32(cur^1, Bw, 768, (c+1)*32)
            cp_commit();
            cp_wait1();
        } else cp_wait0();
        __syncthreads();
        MMA32(cur)
        __syncthreads();
    }
    int rlo = row0 + wm*16 + gp;
    int rhi = rlo + 8;
    int row = odd ? rhi : rlo;
    #pragma unroll
    for (int nn = 0; nn < 4; ++nn) {
        float sx0 = __shfl_xor_sync(0xffffffffu, acc[nn][0], 1);
        float sx1 = __shfl_xor_sync(0xffffffffu, acc[nn][1], 1);
        float sx2 = __shfl_xor_sync(0xffffffffu, acc[nn][2], 1);
        float sx3 = __shfl_xor_sync(0xffffffffu, acc[nn][3], 1);
        float gi, gf, gg, go;
        if (!odd) { gi = acc[nn][0]; gf = acc[nn][1]; gg = sx0; go = sx1; }
        else      { gi = sx2; gf = sx3; gg = acc[nn][2]; go = acc[nn][3]; }
        if (row < Nseq) {
            int ug = (col0 >> 2) + wn*8 + nn*2 + (qn >> 1);
            float4 xv = *(const float4*)&XW[((size_t)row*Lc + tt)*768 + ug*4];
            float I = gi + xv.x, F = gf + xv.y, G = gg + xv.z, O = go + xv.w;
            float cp = Cst[(size_t)row*192 + ug];
            float cn = sigf(F)*cp + sigf(I)*tanhf(G);
            float hn = sigf(O)*tanhf(cn);
            Cst[(size_t)row*192 + ug] = cn;
            Ho[(size_t)row*192 + ug]  = hn;
            hs[((size_t)row*Lc + tt)*384 + d*192 + ug] = hn;
        }
    }
}

// ---------------- convT1d gather-GEMM + bias + residual (double-buffered) ----------------
__global__ void __launch_bounds__(256) convt_gemm(int phase, const float* __restrict__ Tb,
                                                  const float* __restrict__ x0, const float* __restrict__ x1)
{
    __shared__ uint32_t As2[2][64][36];
    __shared__ uint32_t Bs2[2][32][72];
    int s = blockIdx.z;
    int Lc   = phase ? L1 : L0;
    int Qlen = phase ? 512 : 65;
    const float* hs = g_hseq + (size_t)s*HS_S;
    const float* Bw = g_twt + (size_t)(phase*2 + s)*1536*48;
    int row0 = blockIdx.y*64;
    int tid = threadIdx.x;
    MMA_IDS
    float acc[4][4] = {};

    #define CONV_LOAD(buf, kcc) { \
        int ktap = (kcc) / 384; \
        int i0 = (kcc) - ktap*384; \
        int idx = tid; \
        _Pragma("unroll") for (int rep = 0; rep < 2; ++rep) { \
            int rr = idx >> 3, seg = idx & 7; \
            int gr = row0 + rr; \
            int n = gr / Qlen, q = gr - n*Qlen; \
            int l = q - ktap; \
            bool val = (l >= 0 && l < Lc); \
            const float* src = val ? &hs[((size_t)n*Lc + l)*384 + i0 + seg*4] : hs; \
            cp16z(&As2[buf][rr][seg*4], src, val); \
            idx += 256; } \
        idx = tid; \
        _Pragma("unroll") for (int rep = 0; rep < 2; ++rep) { \
            int k = idx >> 4, seg = idx & 15; \
            bool val = (seg*4 < 48); \
            const float* src = val ? &Bw[(size_t)((kcc) + k)*48 + seg*4] : Bw; \
            cp16z(&Bs2[buf][k][seg*4], src, val); \
            idx += 256; } }

    CONV_LOAD(0, 0)
    cp_commit();
    for (int c = 0; c < 48; ++c) {
        int cur = c & 1;
        if (c < 47) {
            CONV_LOAD(cur^1, (c+1)*32)
            cp_commit();
            cp_wait1();
        } else cp_wait0();
        __syncthreads();
        MMA32(cur)
        __syncthreads();
    }
    #undef CONV_LOAD
    int g = phase*2 + s;
    int rlo = row0 + wm*16 + gp;
    #pragma unroll
    for (int nn = 0; nn < 4; ++nn) {
        int cb = wn*32 + nn*8 + 2*qn;
        #pragma unroll
        for (int half = 0; half < 2; ++half) {
            int row = rlo + half*8;
            int n = row / Qlen, q = row - n*Qlen;
            #pragma unroll
            for (int j = 0; j < 2; ++j) {
                int c = cb + j;
                if (c < 48) {
                    float v = acc[nn][half*2 + j] + Tb[g*48 + c];
                    if (phase == 0) {
                        int b = n >> 9, tpos = n & 511;
                        size_t oi = ((size_t)(b*48 + c)*512 + tpos)*65 + q;
                        const float* res = s ? x1 : x0;
                        g_io[(size_t)s*TSZ + oi] = v + res[oi];
                    } else {
                        int b = n / 65, f = n - b*65;
                        size_t oi = ((size_t)(b*48 + c)*512 + q)*65 + f;
                        g_eo[(size_t)s*TSZ + oi] = v + g_io[(size_t)s*TSZ + oi];
                    }
                }
            }
        }
    }
}

// ---------------- q/k/v head projections + leaky + LN ----------------
__global__ void __launch_bounds__(256) qkv_kernel(
    const float* __restrict__ AWqk, const float* __restrict__ Abqk, const float* __restrict__ Aaqk,
    const float* __restrict__ Agqk, const float* __restrict__ Abgqk,
    const float* __restrict__ AWv,  const float* __restrict__ Abv,  const float* __restrict__ Aav,
    const float* __restrict__ Agv,  const float* __restrict__ Abgv)
{
    int t = blockIdx.x, b = blockIdx.y, s = blockIdx.z, tid = threadIdx.x;
    int lane = tid & 31, warp = tid >> 5;
    __shared__ float zs[3120];
    __shared__ float buf[780];
    __shared__ float red[32];
    const float* z = g_eo + (size_t)s*TSZ;
    for (int i = tid; i < 3120; i += 256) {
        int c = i / 65, f = i - c*65;
        zs[i] = z[((size_t)(b*48 + c)*512 + t)*65 + f];
    }
    __syncthreads();
    for (int grp = 0; grp < 12; ++grp) {
        int tensor = grp >> 2, h = grp & 3;
        int nvals;
        const float *W, *bb, *gam, *bet;
        float alpha;
        float* outp;
        bool pad = false;
        if (tensor < 2) {
            nvals = 520;
            int hh = (s*2 + tensor)*4 + h;
            W = AWqk + (size_t)hh*8*48; bb = Abqk + hh*8; alpha = Aaqk[hh];
            gam = Agqk + (size_t)hh*8*65; bet = Abgqk + (size_t)hh*8*65;
            outp = (tensor == 0 ? g_q : g_k) + ((size_t)((s*16 + b*4 + h)*512) + t)*EK;
            pad = true;
        } else {
            nvals = 780;
            int hh = s*4 + h;
            W = AWv + (size_t)hh*12*48; bb = Abv + hh*12; alpha = Aav[hh];
            gam = Agv + (size_t)hh*12*65; bet = Abgv + (size_t)hh*12*65;
            outp = g_v + ((size_t)((s*16 + b*4 + h)*512) + t)*780;
        }
        float ls = 0.f, lq = 0.f;
        for (int idx = tid; idx < nvals; idx += 256) {
            int e = idx / 65, f = idx - e*65;
            float a = bb[e];
            const float* wr = W + e*48;
            #pragma unroll
            for (int c = 0; c < 48; ++c) a += zs[c*65 + f]*wr[c];
            a = a >= 0.f ? a : alpha*a;
            buf[idx] = a; ls += a; lq += a*a;
        }
        #pragma unroll
        for (int o = 16; o; o >>= 1) {
            ls += __shfl_xor_sync(0xffffffffu, ls, o);
            lq += __shfl_xor_sync(0xffffffffu, lq, o);
        }
        if (lane == 0) { red[warp] = ls; red[8 + warp] = lq; }
        __syncthreads();
        if (tid == 0) {
            float a = 0.f, c = 0.f;
            #pragma unroll
            for (int i = 0; i < 8; ++i) { a += red[i]; c += red[8 + i]; }
            red[16] = a; red[17] = c;
        }
        __syncthreads();
        float mu = red[16] / nvals;
        float inv = rsqrtf(red[17] / nvals - mu*mu + EPSLN);
        for (int idx = tid; idx < nvals; idx += 256)
            outp[idx] = (buf[idx] - mu)*inv*gam[idx] + bet[idx];
        if (pad && tid < EK - 520) outp[520 + tid] = 0.f;
        __syncthreads();
    }
}

// ---------------- QK^T (scaled) ----------------
__global__ void __launch_bounds__(256) qk_gemm()
{
    __shared__ uint32_t As[16][72];
    __shared__ uint32_t Bs[16][72];
    int bz = blockIdx.z;
    const float* Q  = g_q + (size_t)bz*512*EK;
    const float* Kf = g_k + (size_t)bz*512*EK;
    float* Co = g_attn + (size_t)bz*512*512;
    int row0 = blockIdx.y*64, col0 = blockIdx.x*64;
    int tid = threadIdx.x;
    MMA_IDS
    float acc[4][4] = {};
    for (int kc = 0; kc < EK; kc += 16) {
        LOAD_A_TRANS(Q, EK, 511)
        {
            int bRow = tid >> 2, bk = (tid & 3)*4;
            float4 v = *(const float4*)&Kf[(size_t)(col0 + bRow)*EK + kc + bk];
            Bs[bk  ][bRow] = __float_as_uint(v.x); Bs[bk+1][bRow] = __float_as_uint(v.y);
            Bs[bk+2][bRow] = __float_as_uint(v.z); Bs[bk+3][bRow] = __float_as_uint(v.w);
        }
        __syncthreads();
        MMA_CHUNK
        __syncthreads();
    }
    float rs = rsqrtf(520.f);
    int rlo = row0 + wm*16 + gp;
    #pragma unroll
    for (int nn = 0; nn < 4; ++nn) {
        int cb = col0 + wn*32 + nn*8 + 2*qn;
        *(float2*)&Co[(size_t)rlo*512 + cb]     = make_float2(acc[nn][0]*rs, acc[nn][1]*rs);
        *(float2*)&Co[(size_t)(rlo+8)*512 + cb] = make_float2(acc[nn][2]*rs, acc[nn][3]*rs);
    }
}

// ---------------- row softmax ----------------
__global__ void __launch_bounds__(256) softmax_rows()
{
    int row = blockIdx.x, bz = blockIdx.y, tid = threadIdx.x;
    float* p = g_attn + (size_t)bz*512*512 + (size_t)row*512;
    __shared__ float sm[512];
    __shared__ float red[256];
    sm[tid] = p[tid]; sm[tid + 256] = p[tid + 256];
    red[tid] = fmaxf(sm[tid], sm[tid + 256]);
    __syncthreads();
    for (int st = 128; st > 0; st >>= 1) {
        if (tid < st) red[tid] = fmaxf(red[tid], red[tid + st]);
        __syncthreads();
    }
    float mx = red[0];
    __syncthreads();
    float e0 = expf(sm[tid] - mx), e1 = expf(sm[tid + 256] - mx);
    red[tid] = e0 + e1;
    __syncthreads();
    for (int st = 128; st > 0; st >>= 1) {
        if (tid < st) red[tid] += red[tid + st];
        __syncthreads();
    }
    float invs = 1.f / red[0];
    p[tid] = e0*invs; p[tid + 256] = e1*invs;
}

// ---------------- P @ V ----------------
__global__ void __launch_bounds__(256) pv_gemm()
{
    __shared__ uint32_t As[16][72];
    __shared__ uint32_t Bs[16][72];
    int bz = blockIdx.z;
    const float* A  = g_attn + (size_t)bz*512*512;
    const float* Bv = g_v + (size_t)bz*512*780;
    float* Co = g_av + (size_t)bz*512*780;
    int row0 = blockIdx.y*64, col0 = blockIdx.x*64;
    int tid = threadIdx.x;
    MMA_IDS
    float acc[4][4] = {};
    for (int kc = 0; kc < 512; kc += 16) {
        LOAD_A_TRANS(A, 512, 511)
        {
            int bk = tid >> 4, bn4 = (tid & 15)*4;
            int col = col0 + bn4;
            float4 v;
            if (col + 3 < 780) {
                v = *(const float4*)&Bv[(size_t)(kc + bk)*780 + col];
            } else {
                v.x = (col     < 780) ? Bv[(size_t)(kc + bk)*780 + col]     : 0.f;
                v.y = (col + 1 < 780) ? Bv[(size_t)(kc + bk)*780 + col + 1] : 0.f;
                v.z = (col + 2 < 780) ? Bv[(size_t)(kc + bk)*780 + col + 2] : 0.f;
                v.w = (col + 3 < 780) ? Bv[(size_t)(kc + bk)*780 + col + 3] : 0.f;
            }
            Bs[bk][bn4  ] = __float_as_uint(v.x); Bs[bk][bn4+1] = __float_as_uint(v.y);
            Bs[bk][bn4+2] = __float_as_uint(v.z); Bs[bk][bn4+3] = __float_as_uint(v.w);
        }
        __syncthreads();
        MMA_CHUNK
        __syncthreads();
    }
    int rlo = row0 + wm*16 + gp;
    #pragma unroll
    for (int nn = 0; nn < 4; ++nn) {
        int cb = col0 + wn*32 + nn*8 + 2*qn;
        #pragma unroll
        for (int j = 0; j < 2; ++j) {
            int col = cb + j;
            if (col < 780) {
                Co[(size_t)rlo*780 + col]     = acc[nn][j];
                Co[(size_t)(rlo+8)*780 + col] = acc[nn][2 + j];
            }
        }
    }
}

// ---------------- output projection + leaky + LN + residual ----------------
__global__ void __launch_bounds__(256) outproj_kernel(
    const float* __restrict__ AWp, const float* __restrict__ Abp, const float* __restrict__ Aap,
    const float* __restrict__ Agp, const float* __restrict__ Abgp, float* __restrict__ dout)
{
    int t = blockIdx.x, b = blockIdx.y, s = blockIdx.z, tid = threadIdx.x;
    int lane = tid & 31, warp = tid >> 5;
    __shared__ float os[3120];
    __shared__ float buf[3120];
    __shared__ float red[32];
    for (int i = tid; i < 3120; i += 256) {
        int c = i / 65, f = i - c*65;
        int h = c / 12, dv = c - h*12;
        os[i] = g_av[((size_t)((s*16 + b*4 + h)*512) + t)*780 + dv*65 + f];
    }
    __syncthreads();
    float alpha = Aap[s];
    float ls = 0.f, lq = 0.f;
    for (int idx = tid; idx < 3120; idx += 256) {
        int o = idx / 65, f = idx - o*65;
        float a = Abp[s*48 + o];
        const float* wr = AWp + (size_t)(s*48 + o)*48;
        #pragma unroll
        for (int c = 0; c < 48; ++c) a += os[c*65 + f]*wr[c];
        a = a >= 0.f ? a : alpha*a;
        buf[idx] = a; ls += a; lq += a*a;
    }
    #pragma unroll
    for (int o = 16; o; o >>= 1) {
        ls += __shfl_xor_sync(0xffffffffu, ls, o);
        lq += __shfl_xor_sync(0xffffffffu, lq, o);
    }
    if (lane == 0) { red[warp] = ls; red[8 + warp] = lq; }
    __syncthreads();
    if (tid == 0) {
        float a = 0.f, c = 0.f;
        #pragma unroll
        for (int i = 0; i < 8; ++i) { a += red[i]; c += red[8 + i]; }
        red[16] = a; red[17] = c;
    }
    __syncthreads();
    float mu = red[16] / 3120.f;
    float inv = rsqrtf(red[17] / 3120.f - mu*mu + EPSLN);
    for (int idx = tid; idx < 3120; idx += 256) {
        int o = idx / 65, f = idx - o*65;
        float v = (buf[idx] - mu)*inv*Agp[(s*48 + o)*65 + f] + Abgp[(s*48 + o)*65 + f]
                + g_eo[(size_t)s*TSZ + ((size_t)(b*48 + o)*512 + t)*65 + f];
        dout[(((size_t)(s*4 + b)*48 + o)*512 + t)*65 + f] = v;
    }
}

// ---------------- host launch ----------------
extern "C" void kernel_launch(void* const* d_in, const int* in_sizes, int n_in,
                              void* d_out, int out_size)
{
    const float* x     = (const float*)d_in[0];
    const float* c2    = (const float*)d_in[1];
    const float* ng    = (const float*)d_in[2];
    const float* nb    = (const float*)d_in[3];
    const float* LWih  = (const float*)d_in[4];
    const float* LWhh  = (const float*)d_in[5];
    const float* Lb    = (const float*)d_in[6];
    const float* TW    = (const float*)d_in[7];
    const float* Tb    = (const float*)d_in[8];
    const float* AWqk  = (const float*)d_in[9];
    const float* Abqk  = (const float*)d_in[10];
    const float* Aaqk  = (const float*)d_in[11];
    const float* Agqk  = (const float*)d_in[12];
    const float* Abgqk = (const float*)d_in[13];
    const float* AWv   = (const float*)d_in[14];
    const float* Abv   = (const float*)d_in[15];
    const float* Aav   = (const float*)d_in[16];
    const float* Agv   = (const float*)d_in[17];
    const float* Abgv  = (const float*)d_in[18];
    const float* AWp   = (const float*)d_in[19];
    const float* Abp   = (const float*)d_in[20];
    const float* Aap   = (const float*)d_in[21];
    const float* Agp   = (const float*)d_in[22];
    const float* Abgp  = (const float*)d_in[23];
    float* out = (float*)d_out;

    pack_weights<<<512, 256>>>(LWih, LWhh, Lb, TW);

    // ---- phase 0: intra ----
    zero_state<<<512, 256>>>();
    ln_unfold_intra<<<dim3(512, 4, 2), 256>>>(x, c2, ng, nb);
    xw_gemm<<<dim3(12, (ROWS0 + 63)/64, 4), 256>>>(0, ROWS0);
    for (int t = 0; t < L0; ++t)
        lstm_step<<<dim3(12, 32, 4), 256>>>(t, 0, t & 1, N0, L0);
    convt_gemm<<<dim3(1, CONV_ROWS/64, 2), 256>>>(0, Tb, x, c2);

    // ---- phase 1: inter ----
    zero_state<<<512, 256>>>();
    ln_unfold_inter<<<dim3(512, 4, 2), 256>>>(ng, nb);
    xw_gemm<<<dim3(12, (ROWS1 + 63)/64, 4), 256>>>(1, ROWS1);
    for (int t = 0; t < L1; ++t)
        lstm_step<<<dim3(12, 5, 4), 256>>>(t, 1, t & 1, N1, L1);
    convt_gemm<<<dim3(1, CONV_ROWS/64, 2), 256>>>(1, Tb, x, c2);

    // ---- attention ----
    qkv_kernel<<<dim3(512, 4, 2), 256>>>(AWqk, Abqk, Aaqk, Agqk, Abgqk,
                                         AWv, Abv, Aav, Agv, Abgv);
    qk_gemm<<<dim3(8, 8, 32), 256>>>();
    softmax_rows<<<dim3(512, 32), 256>>>();
    pv_gemm<<<dim3(13, 8, 32), 256>>>();
    outproj_kernel<<<dim3(512, 4, 2), 256>>>(AWp, Abp, Aap, Agp, Abgp, out);
}

// round 11
// speedup vs baseline: 1.7725x; 1.0902x over previous
#include <cuda_runtime.h>
#include <cuda_bf16.h>
#include <math.h>
#include <stdint.h>

// ---------------- constants ----------------
#define Bb 4
#define Cc 48
#define Tt 512
#define Ff 65
#define L0 62
#define L1 509
#define N0 2048
#define N1 260
#define ROWS0 126976
#define ROWS1 132340
#define ROWSMAX 132340
#define CONV_ROWS 133120
#define XU_S  (ROWSMAX*192)
#define XW_S  ((size_t)ROWSMAX*768)
#define HS_S  ((size_t)ROWSMAX*384)
#define TSZ   (Bb*Cc*Tt*Ff)
#define EK2   544            // padded E*F (520 -> 544, 17 chunks of 32)
#define EPSLN 1e-5f

#define SMEM_XL  ((2*128*36 + 2*32*136)*4)   // 71680
#define SMEM_N64 ((2*128*36 + 2*32*72)*4)    // 55296

// ---------------- device scratch ----------------
__device__ float g_xu[2*XU_S];
__device__ float g_xw[4*XW_S];
__device__ float g_hseq[2*HS_S];
__device__ float g_h[2*4*2048*192];
__device__ float g_c[4*2048*192];
__device__ float g_wihp[8*192*768];
__device__ float g_whhp[8*192*768];
__device__ float g_bp[8*768];
__device__ float g_twt[4*1536*48];
__device__ float g_io[2*TSZ];
__device__ float g_eo[2*TSZ];
__device__ float g_q[(size_t)2*16*512*EK2];          // [bz][t][k]
__device__ float g_k[(size_t)2*16*EK2*512];          // [bz][k][t]  (transposed!)
__device__ float g_v[2*16*512*780];
__device__ float g_attn[(size_t)2*16*512*512];
__device__ float g_av[2*16*512*780];

__device__ __forceinline__ float sigf(float x){ return 1.f/(1.f+expf(-x)); }

__device__ __forceinline__ float tf32r(float x){
    uint32_t r; asm("cvt.rna.tf32.f32 %0, %1;" : "=r"(r) : "f"(x));
    return __uint_as_float(r);
}

__device__ __forceinline__ void mma_tf32(float* c, uint32_t a0, uint32_t a1,
                                         uint32_t a2, uint32_t a3,
                                         uint32_t b0, uint32_t b1){
    asm volatile("mma.sync.aligned.m16n8k8.row.col.f32.tf32.tf32.f32 "
        "{%0,%1,%2,%3}, {%4,%5,%6,%7}, {%8,%9}, {%0,%1,%2,%3};"
        : "+f"(c[0]), "+f"(c[1]), "+f"(c[2]), "+f"(c[3])
        : "r"(a0), "r"(a1), "r"(a2), "r"(a3), "r"(b0), "r"(b1));
}

// cp.async helpers
__device__ __forceinline__ void cp16(void* smem, const void* gmem){
    uint32_t s = (uint32_t)__cvta_generic_to_shared(smem);
    asm volatile("cp.async.ca.shared.global [%0], [%1], 16;\n" :: "r"(s), "l"(gmem) : "memory");
}
__device__ __forceinline__ void cp16z(void* smem, const void* gmem, bool valid){
    uint32_t s = (uint32_t)__cvta_generic_to_shared(smem);
    int sz = valid ? 16 : 0;
    asm volatile("cp.async.ca.shared.global [%0], [%1], 16, %2;\n" :: "r"(s), "l"(gmem), "r"(sz) : "memory");
}
__device__ __forceinline__ void cp_commit(){ asm volatile("cp.async.commit_group;\n" ::: "memory"); }
__device__ __forceinline__ void cp_wait0(){ asm volatile("cp.async.wait_group 0;\n" ::: "memory"); }
__device__ __forceinline__ void cp_wait1(){ asm volatile("cp.async.wait_group 1;\n" ::: "memory"); }

// ------------- shared tile indexing (dynamic smem) -------------
// sA: [2][128][36], sB(XL): [2][32][136], sB(N64): [2][32][72]
#define ASI(buf,m,k)  sA[(buf)*4608 + (m)*36 + (k)]
#define BXL(buf,k,n)  sB[(buf)*4352 + (k)*136 + (n)]
#define BN64(buf,k,n) sB[(buf)*2304 + (k)*72 + (n)]

// common warp/lane ids (requires int tid)
#define WARP_IDS \
    int lane = tid & 31, warp = tid >> 5; \
    int wm = warp >> 1, wn = warp & 1;    \
    int gp = lane >> 2, qn = lane & 3;

// ---- A stage: 128 rows x 32 k, row-major, pitch 36 ----
#define LOAD_A128(buf, Aptr, lda, rowClamp, kcc) { \
    _Pragma("unroll") for (int rep = 0; rep < 4; ++rep) { \
        int idx = tid + rep*256; \
        int row = idx >> 3, seg = idx & 7; \
        int gr = row0 + row; if (gr > (rowClamp)) gr = (rowClamp); \
        cp16(&ASI(buf,row,seg*4), &(Aptr)[(size_t)gr*(lda) + (kcc) + seg*4]); } }

// ---- B stage XL: 32 k x 128 n, pitch 136 ----
#define LOAD_BXL(buf, Bptr, ldb, kcc) { \
    _Pragma("unroll") for (int rep = 0; rep < 4; ++rep) { \
        int idx = tid + rep*256; \
        int k = idx >> 5, seg = idx & 31; \
        cp16(&BXL(buf,k,seg*4), &(Bptr)[(size_t)((kcc) + k)*(ldb) + col0 + seg*4]); } }

#define LOAD_BXL_G(buf, Bptr, ldb, kcc, Ncols) { \
    _Pragma("unroll") for (int rep = 0; rep < 4; ++rep) { \
        int idx = tid + rep*256; \
        int k = idx >> 5, seg = idx & 31; \
        int cc = col0 + seg*4; \
        bool val = (cc < (Ncols)); \
        const float* src = val ? &(Bptr)[(size_t)((kcc) + k)*(ldb) + cc] : (const float*)(Bptr); \
        cp16z(&BXL(buf,k,seg*4), src, val); } }

// ---- B stage N64: 32 k x 64 n, pitch 72 ----
#define LOAD_BN64(buf, Bptr, ldb, kcc) { \
    _Pragma("unroll") for (int rep = 0; rep < 2; ++rep) { \
        int idx = tid + rep*256; \
        int k = idx >> 4, seg = idx & 15; \
        cp16(&BN64(buf,k,seg*4), &(Bptr)[(size_t)((kcc) + k)*(ldb) + col0 + seg*4]); } }

// ---- XL mma: warp tile 32x64, acc[2][8][4] ----
#define MMA_XL(buf) \
    _Pragma("unroll") for (int k8 = 0; k8 < 4; ++k8) { \
        int kb = k8*8 + qn; \
        int am0 = wm*32 + gp; \
        uint32_t a00=ASI(buf,am0,kb),    a01=ASI(buf,am0+8,kb); \
        uint32_t a02=ASI(buf,am0,kb+4),  a03=ASI(buf,am0+8,kb+4); \
        uint32_t a10=ASI(buf,am0+16,kb),   a11=ASI(buf,am0+24,kb); \
        uint32_t a12=ASI(buf,am0+16,kb+4), a13=ASI(buf,am0+24,kb+4); \
        int bn = wn*64 + gp; \
        _Pragma("unroll") for (int nt = 0; nt < 8; ++nt) { \
            uint32_t b0 = BXL(buf,kb,bn+nt*8), b1 = BXL(buf,kb+4,bn+nt*8); \
            mma_tf32(acc[0][nt], a00,a01,a02,a03, b0,b1); \
            mma_tf32(acc[1][nt], a10,a11,a12,a13, b0,b1); } }

// ---- N64 mma: warp tile 32x32, acc[2][4][4] ----
#define MMA_N64(buf) \
    _Pragma("unroll") for (int k8 = 0; k8 < 4; ++k8) { \
        int kb = k8*8 + qn; \
        int am0 = wm*32 + gp; \
        uint32_t a00=ASI(buf,am0,kb),    a01=ASI(buf,am0+8,kb); \
        uint32_t a02=ASI(buf,am0,kb+4),  a03=ASI(buf,am0+8,kb+4); \
        uint32_t a10=ASI(buf,am0+16,kb),   a11=ASI(buf,am0+24,kb); \
        uint32_t a12=ASI(buf,am0+16,kb+4), a13=ASI(buf,am0+24,kb+4); \
        int bn = wn*32 + gp; \
        _Pragma("unroll") for (int nt = 0; nt < 4; ++nt) { \
            uint32_t b0 = BN64(buf,kb,bn+nt*8), b1 = BN64(buf,kb+4,bn+nt*8); \
            mma_tf32(acc[0][nt], a00,a01,a02,a03, b0,b1); \
            mma_tf32(acc[1][nt], a10,a11,a12,a13, b0,b1); } }

// ---------------- weight packing ----------------
__global__ void pack_weights(const float* __restrict__ LWih, const float* __restrict__ LWhh,
                             const float* __restrict__ Lb,   const float* __restrict__ TW)
{
    int stride = gridDim.x * blockDim.x;
    int t0 = blockIdx.x * blockDim.x + threadIdx.x;
    for (int idx = t0; idx < 8*192*768; idx += stride) {
        int w = idx / (192*768);
        int r = idx - w*(192*768);
        int j = r / 768, col = r - j*768;
        int u = col >> 2, gt = col & 3;
        int g = (w>>2)*2 + ((w>>1)&1);
        int d = w & 1;
        size_t src = ((size_t)(g*2+d)*768 + gt*192 + u);
        g_wihp[idx] = tf32r(LWih[src*192 + j]);
        g_whhp[idx] = tf32r(LWhh[src*192 + j]);
    }
    for (int idx = t0; idx < 8*768; idx += stride) {
        int w = idx / 768, col = idx - w*768;
        int u = col >> 2, gt = col & 3;
        int g = (w>>2)*2 + ((w>>1)&1);
        int d = w & 1;
        g_bp[idx] = Lb[(g*2+d)*768 + gt*192 + u];
    }
    for (int idx = t0; idx < 4*1536*48; idx += stride) {
        int g = idx / (1536*48);
        int r = idx - g*(1536*48);
        int kk = r / 48, o = r - kk*48;
        int k = kk / 384, i = kk - k*384;
        g_twt[idx] = tf32r(TW[(((size_t)g*384 + i)*48 + o)*4 + k]);
    }
}

__global__ void zero_state()
{
    int stride = gridDim.x * blockDim.x;
    int t0 = blockIdx.x * blockDim.x + threadIdx.x;
    for (int i = t0; i < 2*4*2048*192; i += stride) g_h[i] = 0.f;
    for (int i = t0; i < 4*2048*192;   i += stride) g_c[i] = 0.f;
}

// ---------------- LN over C + unfold, intra ----------------
__global__ void ln_unfold_intra(const float* __restrict__ x0, const float* __restrict__ x1,
                                const float* __restrict__ ng, const float* __restrict__ nb)
{
    int t = blockIdx.x, b = blockIdx.y, s = blockIdx.z;
    const float* src = s ? x1 : x0;
    __shared__ float zs[48*65];
    __shared__ float mu[65], inv[65];
    int tid = threadIdx.x;
    for (int i = tid; i < 48*65; i += 256) {
        int c = i / 65, f = i - c*65;
        zs[i] = src[((size_t)(b*48 + c)*512 + t)*65 + f];
    }
    __syncthreads();
    if (tid < 65) {
        float s1 = 0.f, s2 = 0.f;
        #pragma unroll
        for (int c = 0; c < 48; ++c) { float v = zs[c*65 + tid]; s1 += v; s2 += v*v; }
        float m = s1 * (1.f/48.f);
        mu[tid] = m;
        inv[tid] = rsqrtf(s2*(1.f/48.f) - m*m + EPSLN);
    }
    __syncthreads();
    size_t n = (size_t)b*512 + t;
    float* outp = g_xu + (size_t)s*XU_S + n*(size_t)L0*192;
    for (int i = tid; i < 48*L0*4; i += 256) {
        int c = i / (L0*4);
        int r = i - c*(L0*4);
        int l = r >> 2, k = r & 3;
        int q = l + k;
        float v = (zs[c*65 + q] - mu[q]) * inv[q] * ng[s*48 + c] + nb[s*48 + c];
        outp[(size_t)l*192 + c*4 + k] = v;
    }
}

// ---------------- LN over C + unfold, inter ----------------
__global__ void ln_unfold_inter(const float* __restrict__ ng, const float* __restrict__ nb)
{
    int t = blockIdx.x, b = blockIdx.y, s = blockIdx.z;
    const float* src = g_io + (size_t)s*TSZ;
    __shared__ float zs[48*65];
    __shared__ float mu[65], inv[65];
    int tid = threadIdx.x;
    for (int i = tid; i < 48*65; i += 256) {
        int c = i / 65, f = i - c*65;
        zs[i] = src[((size_t)(b*48 + c)*512 + t)*65 + f];
    }
    __syncthreads();
    if (tid < 65) {
        float s1 = 0.f, s2 = 0.f;
        #pragma unroll
        for (int c = 0; c < 48; ++c) { float v = zs[c*65 + tid]; s1 += v; s2 += v*v; }
        float m = s1 * (1.f/48.f);
        mu[tid] = m;
        inv[tid] = rsqrtf(s2*(1.f/48.f) - m*m + EPSLN);
    }
    __syncthreads();
    int gi = 2 + s;
    for (int i = tid; i < 48*65; i += 256) {
        int c = i / 65, f = i - c*65;
        float v = (zs[i] - mu[f]) * inv[f] * ng[gi*48 + c] + nb[gi*48 + c];
        size_t n = (size_t)b*65 + f;
        float* outp = g_xu + (size_t)s*XU_S + n*(size_t)L1*192;
        #pragma unroll
        for (int k = 0; k < 4; ++k) {
            int l = t - k;
            if (l >= 0 && l < L1) outp[(size_t)l*192 + c*4 + k] = v;
        }
    }
}

// ---------------- xw = xu @ Wih^T + b   (XL 128x128 tf32 mma) ----------------
__global__ void __launch_bounds__(256, 2) xw_gemm(int phase, int M)
{
    extern __shared__ uint32_t smemu[];
    uint32_t* sA = smemu;
    uint32_t* sB = smemu + 2*4608;
    int combo = blockIdx.z;
    int s = combo >> 1;
    const float* A    = g_xu + (size_t)s*XU_S;
    const float* Bw   = g_wihp + (size_t)(phase*4 + combo)*192*768;
    const float* bias = g_bp + (size_t)(phase*4 + combo)*768;
    float* Co = g_xw + (size_t)combo*XW_S;
    int row0 = blockIdx.y*128, col0 = blockIdx.x*128;
    int tid = threadIdx.x;
    WARP_IDS
    float acc[2][8][4] = {};
    LOAD_A128(0, A, 192, M-1, 0)
    LOAD_BXL(0, Bw, 768, 0)
    cp_commit();
    #pragma unroll
    for (int c = 0; c < 6; ++c) {
        int cur = c & 1;
        if (c < 5) {
            LOAD_A128(cur^1, A, 192, M-1, (c+1)*32)
            LOAD_BXL(cur^1, Bw, 768, (c+1)*32)
            cp_commit();
            cp_wait1();
        } else cp_wait0();
        __syncthreads();
        MMA_XL(cur)
        __syncthreads();
    }
    #pragma unroll
    for (int mt = 0; mt < 2; ++mt) {
        int r = row0 + wm*32 + mt*16 + gp;
        #pragma unroll
        for (int nt = 0; nt < 8; ++nt) {
            int cb = col0 + wn*64 + nt*8 + 2*qn;
            float b0v = bias[cb], b1v = bias[cb+1];
            if (r < M)
                *(float2*)&Co[(size_t)r*768 + cb] = make_float2(acc[mt][nt][0]+b0v, acc[mt][nt][1]+b1v);
            if (r + 8 < M)
                *(float2*)&Co[(size_t)(r+8)*768 + cb] = make_float2(acc[mt][nt][2]+b0v, acc[mt][nt][3]+b1v);
        }
    }
}

// ---------------- fused LSTM step   (M128N64, shfl gate epilogue) ----------------
__global__ void __launch_bounds__(256, 2) lstm_step(int t, int phase, int parity, int Nseq, int Lc)
{
    extern __shared__ uint32_t smemu[];
    uint32_t* sA = smemu;
    uint32_t* sB = smemu + 2*4608;
    int combo = blockIdx.z;
    int s = combo >> 1, d = combo & 1;
    int tt = d ? (Lc - 1 - t) : t;
    const float* Ah = g_h + ((size_t)parity*4 + combo)*2048*192;
    float* Ho       = g_h + ((size_t)(parity ^ 1)*4 + combo)*2048*192;
    float* Cst      = g_c + (size_t)combo*2048*192;
    const float* Bw = g_whhp + (size_t)(phase*4 + combo)*192*768;
    const float* XW = g_xw + (size_t)combo*XW_S;
    float* hs = g_hseq + (size_t)s*HS_S;
    int row0 = blockIdx.y*128, col0 = blockIdx.x*64;
    int tid = threadIdx.x;
    WARP_IDS
    int odd = qn & 1;
    float acc[2][4][4] = {};
    LOAD_A128(0, Ah, 192, Nseq-1, 0)
    LOAD_BN64(0, Bw, 768, 0)
    cp_commit();
    #pragma unroll
    for (int c = 0; c < 6; ++c) {
        int cur = c & 1;
        if (c < 5) {
            LOAD_A128(cur^1, Ah, 192, Nseq-1, (c+1)*32)
            LOAD_BN64(cur^1, Bw, 768, (c+1)*32)
            cp_commit();
            cp_wait1();
        } else cp_wait0();
        __syncthreads();
        MMA_N64(cur)
        __syncthreads();
    }
    #pragma unroll
    for (int mt = 0; mt < 2; ++mt) {
        int rlo = row0 + wm*32 + mt*16 + gp;
        int rhi = rlo + 8;
        int row = odd ? rhi : rlo;
        #pragma unroll
        for (int nt = 0; nt < 4; ++nt) {
            float sx0 = __shfl_xor_sync(0xffffffffu, acc[mt][nt][0], 1);
            float sx1 = __shfl_xor_sync(0xffffffffu, acc[mt][nt][1], 1);
            float sx2 = __shfl_xor_sync(0xffffffffu, acc[mt][nt][2], 1);
            float sx3 = __shfl_xor_sync(0xffffffffu, acc[mt][nt][3], 1);
            float gi, gf, gg, go;
            if (!odd) { gi = acc[mt][nt][0]; gf = acc[mt][nt][1]; gg = sx0; go = sx1; }
            else      { gi = sx2; gf = sx3; gg = acc[mt][nt][2]; go = acc[mt][nt][3]; }
            if (row < Nseq) {
                int ug = (col0 >> 2) + wn*8 + nt*2 + (qn >> 1);
                float4 xv = *(const float4*)&XW[((size_t)row*Lc + tt)*768 + ug*4];
                float I = gi + xv.x, F = gf + xv.y, G = gg + xv.z, O = go + xv.w;
                float cp = Cst[(size_t)row*192 + ug];
                float cn = sigf(F)*cp + sigf(I)*tanhf(G);
                float hn = sigf(O)*tanhf(cn);
                Cst[(size_t)row*192 + ug] = cn;
                Ho[(size_t)row*192 + ug]  = hn;
                hs[((size_t)row*Lc + tt)*384 + d*192 + ug] = hn;
            }
        }
    }
}

// ---------------- convT1d gather-GEMM + bias + residual  (M128N64) ----------------
__global__ void __launch_bounds__(256, 2) convt_gemm(int phase, const float* __restrict__ Tb,
                                                     const float* __restrict__ x0, const float* __restrict__ x1)
{
    extern __shared__ uint32_t smemu[];
    uint32_t* sA = smemu;
    uint32_t* sB = smemu + 2*4608;
    int s = blockIdx.z;
    int Lc   = phase ? L1 : L0;
    int Qlen = phase ? 512 : 65;
    const float* hs = g_hseq + (size_t)s*HS_S;
    const float* Bw = g_twt + (size_t)(phase*2 + s)*1536*48;
    int row0 = blockIdx.y*128, col0 = 0;
    int tid = threadIdx.x;
    WARP_IDS
    float acc[2][4][4] = {};

    #define CONV_LOAD(buf, kcc) { \
        int ktap = (kcc) / 384; \
        int i0 = (kcc) - ktap*384; \
        _Pragma("unroll") for (int rep = 0; rep < 4; ++rep) { \
            int idx = tid + rep*256; \
            int rr = idx >> 3, seg = idx & 7; \
            int gr = row0 + rr; \
            int n = gr / Qlen, q = gr - n*Qlen; \
            int l = q - ktap; \
            bool val = (l >= 0 && l < Lc); \
            const float* src = val ? &hs[((size_t)n*Lc + l)*384 + i0 + seg*4] : hs; \
            cp16z(&ASI(buf,rr,seg*4), src, val); } \
        _Pragma("unroll") for (int rep = 0; rep < 2; ++rep) { \
            int idx = tid + rep*256; \
            int k = idx >> 4, seg = idx & 15; \
            bool val = (seg*4 < 48); \
            const float* src = val ? &Bw[(size_t)((kcc) + k)*48 + seg*4] : Bw; \
            cp16z(&BN64(buf,k,seg*4), src, val); } }

    CONV_LOAD(0, 0)
    cp_commit();
    for (int c = 0; c < 48; ++c) {
        int cur = c & 1;
        if (c < 47) {
            CONV_LOAD(cur^1, (c+1)*32)
            cp_commit();
            cp_wait1();
        } else cp_wait0();
        __syncthreads();
        MMA_N64(cur)
        __syncthreads();
    }
    #undef CONV_LOAD
    int g = phase*2 + s;
    #pragma unroll
    for (int mt = 0; mt < 2; ++mt) {
        int rbase = row0 + wm*32 + mt*16 + gp;
        #pragma unroll
        for (int nt = 0; nt < 4; ++nt) {
            int cb = wn*32 + nt*8 + 2*qn;
            #pragma unroll
            for (int half = 0; half < 2; ++half) {
                int row = rbase + half*8;
                int n = row / Qlen, q = row - n*Qlen;
                #pragma unroll
                for (int j = 0; j < 2; ++j) {
                    int c = cb + j;
                    if (c < 48) {
                        float v = acc[mt][nt][half*2 + j] + Tb[g*48 + c];
                        if (phase == 0) {
                            int b = n >> 9, tpos = n & 511;
                            size_t oi = ((size_t)(b*48 + c)*512 + tpos)*65 + q;
                            const float* res = s ? x1 : x0;
                            g_io[(size_t)s*TSZ + oi] = v + res[oi];
                        } else {
                            int b = n / 65, f = n - b*65;
                            size_t oi = ((size_t)(b*48 + c)*512 + q)*65 + f;
                            g_eo[(size_t)s*TSZ + oi] = v + g_io[(size_t)s*TSZ + oi];
                        }
                    }
                }
            }
        }
    }
}

// ---------------- q/k/v head projections + leaky + LN (K written transposed) ----------------
__global__ void __launch_bounds__(256) qkv_kernel(
    const float* __restrict__ AWqk, const float* __restrict__ Abqk, const float* __restrict__ Aaqk,
    const float* __restrict__ Agqk, const float* __restrict__ Abgqk,
    const float* __restrict__ AWv,  const float* __restrict__ Abv,  const float* __restrict__ Aav,
    const float* __restrict__ Agv,  const float* __restrict__ Abgv)
{
    int t = blockIdx.x, b = blockIdx.y, s = blockIdx.z, tid = threadIdx.x;
    int lane = tid & 31, warp = tid >> 5;
    __shared__ float zs[3120];
    __shared__ float buf[780];
    __shared__ float red[32];
    const float* z = g_eo + (size_t)s*TSZ;
    for (int i = tid; i < 3120; i += 256) {
        int c = i / 65, f = i - c*65;
        zs[i] = z[((size_t)(b*48 + c)*512 + t)*65 + f];
    }
    __syncthreads();
    for (int grp = 0; grp < 12; ++grp) {
        int tensor = grp >> 2, h = grp & 3;
        int nvals;
        const float *W, *bb, *gam, *bet;
        float alpha;
        if (tensor < 2) {
            nvals = 520;
            int hh = (s*2 + tensor)*4 + h;
            W = AWqk + (size_t)hh*8*48; bb = Abqk + hh*8; alpha = Aaqk[hh];
            gam = Agqk + (size_t)hh*8*65; bet = Abgqk + (size_t)hh*8*65;
        } else {
            nvals = 780;
            int hh = s*4 + h;
            W = AWv + (size_t)hh*12*48; bb = Abv + hh*12; alpha = Aav[hh];
            gam = Agv + (size_t)hh*12*65; bet = Abgv + (size_t)hh*12*65;
        }
        float ls = 0.f, lq = 0.f;
        for (int idx = tid; idx < nvals; idx += 256) {
            int e = idx / 65, f = idx - e*65;
            float a = bb[e];
            const float* wr = W + e*48;
            #pragma unroll
            for (int c = 0; c < 48; ++c) a += zs[c*65 + f]*wr[c];
            a = a >= 0.f ? a : alpha*a;
            buf[idx] = a; ls += a; lq += a*a;
        }
        #pragma unroll
        for (int o = 16; o; o >>= 1) {
            ls += __shfl_xor_sync(0xffffffffu, ls, o);
            lq += __shfl_xor_sync(0xffffffffu, lq, o);
        }
        if (lane == 0) { red[warp] = ls; red[8 + warp] = lq; }
        __syncthreads();
        if (tid == 0) {
            float a = 0.f, c = 0.f;
            #pragma unroll
            for (int i = 0; i < 8; ++i) { a += red[i]; c += red[8 + i]; }
            red[16] = a; red[17] = c;
        }
        __syncthreads();
        float mu = red[16] / nvals;
        float inv = rsqrtf(red[17] / nvals - mu*mu + EPSLN);
        int bz = s*16 + b*4 + h;
        if (tensor == 0) {
            float* outp = g_q + ((size_t)bz*512 + t)*EK2;
            for (int idx = tid; idx < nvals; idx += 256)
                outp[idx] = (buf[idx] - mu)*inv*gam[idx] + bet[idx];
            if (tid < EK2 - 520) outp[520 + tid] = 0.f;
        } else if (tensor == 1) {
            float* outp = g_k + (size_t)bz*EK2*512;   // [k][t]
            for (int idx = tid; idx < nvals; idx += 256)
                outp[(size_t)idx*512 + t] = (buf[idx] - mu)*inv*gam[idx] + bet[idx];
            if (tid < EK2 - 520) outp[(size_t)(520 + tid)*512 + t] = 0.f;
        } else {
            float* outp = g_v + ((size_t)bz*512 + t)*780;
            for (int idx = tid; idx < nvals; idx += 256)
                outp[idx] = (buf[idx] - mu)*inv*gam[idx] + bet[idx];
        }
        __syncthreads();
    }
}

// ---------------- QK^T (scaled, XL) ----------------
__global__ void __launch_bounds__(256, 2) qk_gemm()
{
    extern __shared__ uint32_t smemu[];
    uint32_t* sA = smemu;
    uint32_t* sB = smemu + 2*4608;
    int bz = blockIdx.z;
    const float* Q  = g_q + (size_t)bz*512*EK2;
    const float* Kt = g_k + (size_t)bz*EK2*512;   // [k][t]
    float* Co = g_attn + (size_t)bz*512*512;
    int row0 = blockIdx.y*128, col0 = blockIdx.x*128;
    int tid = threadIdx.x;
    WARP_IDS
    float acc[2][8][4] = {};
    LOAD_A128(0, Q, EK2, 511, 0)
    LOAD_BXL(0, Kt, 512, 0)
    cp_commit();
    for (int c = 0; c < 17; ++c) {
        int cur = c & 1;
        if (c < 16) {
            LOAD_A128(cur^1, Q, EK2, 511, (c+1)*32)
            LOAD_BXL(cur^1, Kt, 512, (c+1)*32)
            cp_commit();
            cp_wait1();
        } else cp_wait0();
        __syncthreads();
        MMA_XL(cur)
        __syncthreads();
    }
    float rs = rsqrtf(520.f);
    #pragma unroll
    for (int mt = 0; mt < 2; ++mt) {
        int r = row0 + wm*32 + mt*16 + gp;
        #pragma unroll
        for (int nt = 0; nt < 8; ++nt) {
            int cb = col0 + wn*64 + nt*8 + 2*qn;
            *(float2*)&Co[(size_t)r*512 + cb]     = make_float2(acc[mt][nt][0]*rs, acc[mt][nt][1]*rs);
            *(float2*)&Co[(size_t)(r+8)*512 + cb] = make_float2(acc[mt][nt][2]*rs, acc[mt][nt][3]*rs);
        }
    }
}

// ---------------- row softmax ----------------
__global__ void __launch_bounds__(256) softmax_rows()
{
    int row = blockIdx.x, bz = blockIdx.y, tid = threadIdx.x;
    float* p = g_attn + (size_t)bz*512*512 + (size_t)row*512;
    __shared__ float sm[512];
    __shared__ float red[256];
    sm[tid] = p[tid]; sm[tid + 256] = p[tid + 256];
    red[tid] = fmaxf(sm[tid], sm[tid + 256]);
    __syncthreads();
    for (int st = 128; st > 0; st >>= 1) {
        if (tid < st) red[tid] = fmaxf(red[tid], red[tid + st]);
        __syncthreads();
    }
    float mx = red[0];
    __syncthreads();
    float e0 = expf(sm[tid] - mx), e1 = expf(sm[tid + 256] - mx);
    red[tid] = e0 + e1;
    __syncthreads();
    for (int st = 128; st > 0; st >>= 1) {
        if (tid < st) red[tid] += red[tid + st];
        __syncthreads();
    }
    float invs = 1.f / red[0];
    p[tid] = e0*invs; p[tid + 256] = e1*invs;
}

// ---------------- P @ V (XL) ----------------
__global__ void __launch_bounds__(256, 2) pv_gemm()
{
    extern __shared__ uint32_t smemu[];
    uint32_t* sA = smemu;
    uint32_t* sB = smemu + 2*4608;
    int bz = blockIdx.z;
    const float* A  = g_attn + (size_t)bz*512*512;
    const float* Bv = g_v + (size_t)bz*512*780;
    float* Co = g_av + (size_t)bz*512*780;
    int row0 = blockIdx.y*128, col0 = blockIdx.x*128;
    int tid = threadIdx.x;
    WARP_IDS
    float acc[2][8][4] = {};
    LOAD_A128(0, A, 512, 511, 0)
    LOAD_BXL_G(0, Bv, 780, 0, 780)
    cp_commit();
    for (int c = 0; c < 16; ++c) {
        int cur = c & 1;
        if (c < 15) {
            LOAD_A128(cur^1, A, 512, 511, (c+1)*32)
            LOAD_BXL_G(cur^1, Bv, 780, (c+1)*32, 780)
            cp_commit();
            cp_wait1();
        } else cp_wait0();
        __syncthreads();
        MMA_XL(cur)
        __syncthreads();
    }
    #pragma unroll
    for (int mt = 0; mt < 2; ++mt) {
        int r = row0 + wm*32 + mt*16 + gp;
        #pragma unroll
        for (int nt = 0; nt < 8; ++nt) {
            int cb = col0 + wn*64 + nt*8 + 2*qn;
            #pragma unroll
            for (int j = 0; j < 2; ++j) {
                int col = cb + j;
                if (col < 780) {
                    Co[(size_t)r*780 + col]     = acc[mt][nt][j];
                    Co[(size_t)(r+8)*780 + col] = acc[mt][nt][2 + j];
                }
            }
        }
    }
}

// ---------------- output projection + leaky + LN + residual ----------------
__global__ void __launch_bounds__(256) outproj_kernel(
    const float* __restrict__ AWp, const float* __restrict__ Abp, const float* __restrict__ Aap,
    const float* __restrict__ Agp, const float* __restrict__ Abgp, float* __restrict__ dout)
{
    int t = blockIdx.x, b = blockIdx.y, s = blockIdx.z, tid = threadIdx.x;
    int lane = tid & 31, warp = tid >> 5;
    __shared__ float os[3120];
    __shared__ float buf[3120];
    __shared__ float red[32];
    for (int i = tid; i < 3120; i += 256) {
        int c = i / 65, f = i - c*65;
        int h = c / 12, dv = c - h*12;
        os[i] = g_av[((size_t)((s*16 + b*4 + h)*512) + t)*780 + dv*65 + f];
    }
    __syncthreads();
    float alpha = Aap[s];
    float ls = 0.f, lq = 0.f;
    for (int idx = tid; idx < 3120; idx += 256) {
        int o = idx / 65, f = idx - o*65;
        float a = Abp[s*48 + o];
        const float* wr = AWp + (size_t)(s*48 + o)*48;
        #pragma unroll
        for (int c = 0; c < 48; ++c) a += os[c*65 + f]*wr[c];
        a = a >= 0.f ? a : alpha*a;
        buf[idx] = a; ls += a; lq += a*a;
    }
    #pragma unroll
    for (int o = 16; o; o >>= 1) {
        ls += __shfl_xor_sync(0xffffffffu, ls, o);
        lq += __shfl_xor_sync(0xffffffffu, lq, o);
    }
    if (lane == 0) { red[warp] = ls; red[8 + warp] = lq; }
    __syncthreads();
    if (tid == 0) {
        float a = 0.f, c = 0.f;
        #pragma unroll
        for (int i = 0; i < 8; ++i) { a += red[i]; c += red[8 + i]; }
        red[16] = a; red[17] = c;
    }
    __syncthreads();
    float mu = red[16] / 3120.f;
    float inv = rsqrtf(red[17] / 3120.f - mu*mu + EPSLN);
    for (int idx = tid; idx < 3120; idx += 256) {
        int o = idx / 65, f = idx - o*65;
        float v = (buf[idx] - mu)*inv*Agp[(s*48 + o)*65 + f] + Abgp[(s*48 + o)*65 + f]
                + g_eo[(size_t)s*TSZ + ((size_t)(b*48 + o)*512 + t)*65 + f];
        dout[(((size_t)(s*4 + b)*48 + o)*512 + t)*65 + f] = v;
    }
}

// ---------------- host launch ----------------
extern "C" void kernel_launch(void* const* d_in, const int* in_sizes, int n_in,
                              void* d_out, int out_size)
{
    const float* x     = (const float*)d_in[0];
    const float* c2    = (const float*)d_in[1];
    const float* ng    = (const float*)d_in[2];
    const float* nb    = (const float*)d_in[3];
    const float* LWih  = (const float*)d_in[4];
    const float* LWhh  = (const float*)d_in[5];
    const float* Lb    = (const float*)d_in[6];
    const float* TW    = (const float*)d_in[7];
    const float* Tb    = (const float*)d_in[8];
    const float* AWqk  = (const float*)d_in[9];
    const float* Abqk  = (const float*)d_in[10];
    const float* Aaqk  = (const float*)d_in[11];
    const float* Agqk  = (const float*)d_in[12];
    const float* Abgqk = (const float*)d_in[13];
    const float* AWv   = (const float*)d_in[14];
    const float* Abv   = (const float*)d_in[15];
    const float* Aav   = (const float*)d_in[16];
    const float* Agv   = (const float*)d_in[17];
    const float* Abgv  = (const float*)d_in[18];
    const float* AWp   = (const float*)d_in[19];
    const float* Abp   = (const float*)d_in[20];
    const float* Aap   = (const float*)d_in[21];
    const float* Agp   = (const float*)d_in[22];
    const float* Abgp  = (const float*)d_in[23];
    float* out = (float*)d_out;

    cudaFuncSetAttribute(xw_gemm,   cudaFuncAttributeMaxDynamicSharedMemorySize, SMEM_XL);
    cudaFuncSetAttribute(qk_gemm,   cudaFuncAttributeMaxDynamicSharedMemorySize, SMEM_XL);
    cudaFuncSetAttribute(pv_gemm,   cudaFuncAttributeMaxDynamicSharedMemorySize, SMEM_XL);
    cudaFuncSetAttribute(lstm_step, cudaFuncAttributeMaxDynamicSharedMemorySize, SMEM_N64);
    cudaFuncSetAttribute(convt_gemm,cudaFuncAttributeMaxDynamicSharedMemorySize, SMEM_N64);

    pack_weights<<<512, 256>>>(LWih, LWhh, Lb, TW);

    // ---- phase 0: intra ----
    zero_state<<<512, 256>>>();
    ln_unfold_intra<<<dim3(512, 4, 2), 256>>>(x, c2, ng, nb);
    xw_gemm<<<dim3(6, (ROWS0 + 127)/128, 4), 256, SMEM_XL>>>(0, ROWS0);
    for (int t = 0; t < L0; ++t)
        lstm_step<<<dim3(12, 16, 4), 256, SMEM_N64>>>(t, 0, t & 1, N0, L0);
    convt_gemm<<<dim3(1, CONV_ROWS/128, 2), 256, SMEM_N64>>>(0, Tb, x, c2);

    // ---- phase 1: inter ----
    zero_state<<<512, 256>>>();
    ln_unfold_inter<<<dim3(512, 4, 2), 256>>>(ng, nb);
    xw_gemm<<<dim3(6, (ROWS1 + 127)/128, 4), 256, SMEM_XL>>>(1, ROWS1);
    for (int t = 0; t < L1; ++t)
        lstm_step<<<dim3(12, (N1 + 127)/128, 4), 256, SMEM_N64>>>(t, 1, t & 1, N1, L1);
    convt_gemm<<<dim3(1, CONV_ROWS/128, 2), 256, SMEM_N64>>>(1, Tb, x, c2);

    // ---- attention ----
    qkv_kernel<<<dim3(512, 4, 2), 256>>>(AWqk, Abqk, Aaqk, Agqk, Abgqk,
                                         AWv, Abv, Aav, Agv, Abgv);
    qk_gemm<<<dim3(4, 4, 32), 256, SMEM_XL>>>();
    softmax_rows<<<dim3(512, 32), 256>>>();
    pv_gemm<<<dim3(7, 4, 32), 256, SMEM_XL>>>();
    outproj_kernel<<<dim3(512, 4, 2), 256>>>(AWp, Abp, Aap, Agp, Abgp, out);
}